// round 5
// baseline (speedup 1.0000x reference)
#include <cuda_runtime.h>
#include <cstdint>
#include <cstddef>

// Problem constants
#define BB    64
#define VV    32000
#define EE    512
#define HH    1024
#define G3    3072
#define TT    64
#define DINIT 768
#define DATT  256
#define NT    256          // logits N-tile per CTA

// ---------------- scratch (device globals; no allocations allowed) ----------
__device__ float g_h[BB * HH];                 // hidden state (in-place update)
__device__ float g_gi[BB * G3];                // x @ W_ih^T + b_ih
__device__ float g_gh[BB * G3];                // h @ W_hh^T + b_hh
__device__ int   g_sid[BB];                    // sampled ids (feedback)

// ---------------- f32x2 packed math helpers ---------------------------------
__device__ __forceinline__ unsigned long long pack2(float lo, float hi) {
    unsigned long long r;
    asm("mov.b64 %0, {%1,%2};" : "=l"(r) : "f"(lo), "f"(hi));
    return r;
}
__device__ __forceinline__ unsigned long long fma2(unsigned long long a,
                                                   unsigned long long b,
                                                   unsigned long long c) {
    unsigned long long d;
    asm("fma.rn.f32x2 %0, %1, %2, %3;" : "=l"(d) : "l"(a), "l"(b), "l"(c));
    return d;
}
__device__ __forceinline__ float2 unpack2(unsigned long long v) {
    float2 f;
    asm("mov.b64 {%0,%1}, %2;" : "=f"(f.x), "=f"(f.y) : "l"(v));
    return f;
}

// ---------------- threefry2x32 (exact JAX schedule) --------------------------
__host__ __device__ static inline void tf2x32(unsigned k0, unsigned k1,
                                              unsigned x0, unsigned x1,
                                              unsigned* o0, unsigned* o1) {
    unsigned ks2 = k0 ^ k1 ^ 0x1BD11BDAu;
#define TF_RND(R) { x0 += x1; x1 = (x1 << (R)) | (x1 >> (32 - (R))); x1 ^= x0; }
    x0 += k0; x1 += k1;
    TF_RND(13) TF_RND(15) TF_RND(26) TF_RND(6)
    x0 += k1;  x1 += ks2 + 1u;
    TF_RND(17) TF_RND(29) TF_RND(16) TF_RND(24)
    x0 += ks2; x1 += k0 + 2u;
    TF_RND(13) TF_RND(15) TF_RND(26) TF_RND(6)
    x0 += k0;  x1 += k1 + 3u;
    TF_RND(17) TF_RND(29) TF_RND(16) TF_RND(24)
    x0 += k1;  x1 += ks2 + 4u;
    TF_RND(13) TF_RND(15) TF_RND(26) TF_RND(6)
    x0 += ks2; x1 += k0 + 5u;
#undef TF_RND
    *o0 = x0; *o1 = x1;
}

// JAX partitionable random_bits (32-bit): counter = 64-bit flat index e
// (hi = 0 for our sizes), draw = o0 ^ o1.
__device__ __forceinline__ unsigned jax_bits32(unsigned k0, unsigned k1,
                                               unsigned e) {
    unsigned o0, o1;
    tf2x32(k0, k1, 0u, e, &o0, &o1);
    return o0 ^ o1;
}

// JAX uniform->gumbel
__device__ __forceinline__ float gumbel_from_bits(unsigned bits) {
    float u = __uint_as_float((bits >> 9) | 0x3f800000u) - 1.0f;
    u = u + 1.17549435082228750797e-38f;   // == max(tiny, u0) in fp32
    return -logf(-logf(u));
}

__device__ __forceinline__ unsigned orderf(float f) {
    unsigned u = __float_as_uint(f);
    return (u & 0x80000000u) ? ~u : (u | 0x80000000u);
}

// ---------------- init: h0 = concat(init_hidden, att_embedding) --------------
__global__ void init_kernel(const float* __restrict__ init_hidden,
                            const float* __restrict__ att) {
    int i = blockIdx.x * blockDim.x + threadIdx.x;   // [0, B*H)
    int b = i / HH, u = i % HH;
    g_h[i] = (u < DINIT) ? init_hidden[b * DINIT + u]
                         : att[b * DATT + (u - DINIT)];
}

// ---------------- gates SGEMM: 64x64 tiles (f32x2) ---------------------------
// blocks [0,48)   -> gi = X(gathered emb rows) @ W_ih^T + b_ih
// blocks [48,96)  -> gh = h @ W_hh^T + b_hh
__global__ __launch_bounds__(256) void gates_gemm(
    const float* __restrict__ emb,
    const int*   __restrict__ inputs,
    const float* __restrict__ Wih, const float* __restrict__ Whh,
    const float* __restrict__ bih, const float* __restrict__ bhh,
    int t) {

    __shared__ __align__(16) float As[16][64];
    __shared__ __align__(16) float Bs[16][64];
    __shared__ const float* rowp[64];

    const float* W; const float* bias; float* C;
    int K, ncol0;
    bool gather = false;
    if (blockIdx.x < 48) {
        gather = true; W = Wih; bias = bih; C = g_gi;
        K = EE; ncol0 = blockIdx.x * 64;
    } else {
        W = Whh; bias = bhh; C = g_gh;
        K = HH; ncol0 = (blockIdx.x - 48) * 64;
    }

    const int tid = threadIdx.x;
    if (tid < 64) {
        if (gather) {
            int sid = (t == 0) ? inputs[tid] : g_sid[tid];
            rowp[tid] = emb + (size_t)sid * EE;
        } else {
            rowp[tid] = g_h + (size_t)tid * HH;
        }
    }
    __syncthreads();

    const int lm = tid >> 2;          // row loaded (0..63)
    const int lk = (tid & 3) << 2;    // k offset (0,4,8,12)

    {
        float4 a  = *(const float4*)(rowp[lm] + lk);
        float4 bt = *(const float4*)(W + (size_t)(ncol0 + lm) * K + lk);
        As[lk + 0][lm] = a.x;  As[lk + 1][lm] = a.y;
        As[lk + 2][lm] = a.z;  As[lk + 3][lm] = a.w;
        Bs[lk + 0][lm] = bt.x; Bs[lk + 1][lm] = bt.y;
        Bs[lk + 2][lm] = bt.z; Bs[lk + 3][lm] = bt.w;
    }
    __syncthreads();

    const int tx = tid & 15;   // cols ncol0 + tx*4 .. +3
    const int ty = tid >> 4;   // rows ty*4 .. +3

    unsigned long long acc[2][4];
#pragma unroll
    for (int p = 0; p < 2; ++p)
#pragma unroll
        for (int n = 0; n < 4; ++n) acc[p][n] = 0ull;

    const int KT = K >> 4;
    for (int kt = 0; kt < KT; ++kt) {
        float4 an, bn;
        if (kt + 1 < KT) {
            int k0 = (kt + 1) << 4;
            an = *(const float4*)(rowp[lm] + k0 + lk);
            bn = *(const float4*)(W + (size_t)(ncol0 + lm) * K + k0 + lk);
        }
#pragma unroll
        for (int kk = 0; kk < 16; ++kk) {
            ulonglong2 av = *(const ulonglong2*)&As[kk][ty << 2];
            float4     bv = *(const float4*)&Bs[kk][tx << 2];
            unsigned long long b0 = pack2(bv.x, bv.x);
            unsigned long long b1 = pack2(bv.y, bv.y);
            unsigned long long b2 = pack2(bv.z, bv.z);
            unsigned long long b3 = pack2(bv.w, bv.w);
            acc[0][0] = fma2(av.x, b0, acc[0][0]);
            acc[0][1] = fma2(av.x, b1, acc[0][1]);
            acc[0][2] = fma2(av.x, b2, acc[0][2]);
            acc[0][3] = fma2(av.x, b3, acc[0][3]);
            acc[1][0] = fma2(av.y, b0, acc[1][0]);
            acc[1][1] = fma2(av.y, b1, acc[1][1]);
            acc[1][2] = fma2(av.y, b2, acc[1][2]);
            acc[1][3] = fma2(av.y, b3, acc[1][3]);
        }
        __syncthreads();
        if (kt + 1 < KT) {
            As[lk + 0][lm] = an.x; As[lk + 1][lm] = an.y;
            As[lk + 2][lm] = an.z; As[lk + 3][lm] = an.w;
            Bs[lk + 0][lm] = bn.x; Bs[lk + 1][lm] = bn.y;
            Bs[lk + 2][lm] = bn.z; Bs[lk + 3][lm] = bn.w;
            __syncthreads();
        }
    }

    const int m0 = ty << 2;
    const int n0 = ncol0 + (tx << 2);
    float4 bsv = *(const float4*)(bias + n0);
#pragma unroll
    for (int p = 0; p < 2; ++p) {
        float2 c0 = unpack2(acc[p][0]);
        float2 c1 = unpack2(acc[p][1]);
        float2 c2 = unpack2(acc[p][2]);
        float2 c3 = unpack2(acc[p][3]);
        int r0 = m0 + 2 * p;
        float4 w0 = make_float4(c0.x + bsv.x, c1.x + bsv.y, c2.x + bsv.z, c3.x + bsv.w);
        float4 w1 = make_float4(c0.y + bsv.x, c1.y + bsv.y, c2.y + bsv.z, c3.y + bsv.w);
        *(float4*)(C + (size_t)r0 * G3 + n0)       = w0;
        *(float4*)(C + (size_t)(r0 + 1) * G3 + n0) = w1;
    }
}

// ---------------- logits SGEMM: 64x256 CTA tile, 8x8 per thread --------------
// grid = 125, block = 256. C = h @ W_out^T + b_out
__global__ __launch_bounds__(256) void logits_gemm(
    const float* __restrict__ Wout, const float* __restrict__ bout,
    float* __restrict__ out) {

    __shared__ __align__(16) float As[16][64];
    __shared__ __align__(16) float Bs[16][NT];

    const int tid   = threadIdx.x;
    const int ncol0 = blockIdx.x * NT;

    const int lm = tid >> 2;          // A row loaded (0..63)
    const int lk = (tid & 3) << 2;    // A k offset (0,4,8,12)
    const float* Wrow = Wout + (size_t)(ncol0 + tid) * HH;   // B row n = tid

    // first tile
    {
        float4 a = *(const float4*)(g_h + (size_t)lm * HH + lk);
        As[lk + 0][lm] = a.x; As[lk + 1][lm] = a.y;
        As[lk + 2][lm] = a.z; As[lk + 3][lm] = a.w;
#pragma unroll
        for (int j = 0; j < 4; ++j) {
            float4 b = *(const float4*)(Wrow + 4 * j);
            Bs[4 * j + 0][tid] = b.x; Bs[4 * j + 1][tid] = b.y;
            Bs[4 * j + 2][tid] = b.z; Bs[4 * j + 3][tid] = b.w;
        }
    }
    __syncthreads();

    const int tx = tid & 31;   // n-group: cols ncol0 + tx*8 .. +7
    const int ty = tid >> 5;   // m-group: rows ty*8 .. +7 (4 packed pairs)

    unsigned long long acc[4][8];
#pragma unroll
    for (int p = 0; p < 4; ++p)
#pragma unroll
        for (int n = 0; n < 8; ++n) acc[p][n] = 0ull;

    const int KT = HH >> 4;    // 64 k-tiles
    for (int kt = 0; kt < KT; ++kt) {
        float4 an, bn0, bn1, bn2, bn3;
        if (kt + 1 < KT) {
            int k0 = (kt + 1) << 4;
            an  = *(const float4*)(g_h + (size_t)lm * HH + k0 + lk);
            bn0 = *(const float4*)(Wrow + k0 + 0);
            bn1 = *(const float4*)(Wrow + k0 + 4);
            bn2 = *(const float4*)(Wrow + k0 + 8);
            bn3 = *(const float4*)(Wrow + k0 + 12);
        }
#pragma unroll
        for (int kk = 0; kk < 16; ++kk) {
            ulonglong2 av01 = *(const ulonglong2*)&As[kk][ty << 3];
            ulonglong2 av23 = *(const ulonglong2*)&As[kk][(ty << 3) + 4];
            float4 bv0 = *(const float4*)&Bs[kk][tx << 3];
            float4 bv1 = *(const float4*)&Bs[kk][(tx << 3) + 4];
            unsigned long long b0 = pack2(bv0.x, bv0.x);
            unsigned long long b1 = pack2(bv0.y, bv0.y);
            unsigned long long b2 = pack2(bv0.z, bv0.z);
            unsigned long long b3 = pack2(bv0.w, bv0.w);
            unsigned long long b4 = pack2(bv1.x, bv1.x);
            unsigned long long b5 = pack2(bv1.y, bv1.y);
            unsigned long long b6 = pack2(bv1.z, bv1.z);
            unsigned long long b7 = pack2(bv1.w, bv1.w);
            acc[0][0] = fma2(av01.x, b0, acc[0][0]);
            acc[0][1] = fma2(av01.x, b1, acc[0][1]);
            acc[0][2] = fma2(av01.x, b2, acc[0][2]);
            acc[0][3] = fma2(av01.x, b3, acc[0][3]);
            acc[0][4] = fma2(av01.x, b4, acc[0][4]);
            acc[0][5] = fma2(av01.x, b5, acc[0][5]);
            acc[0][6] = fma2(av01.x, b6, acc[0][6]);
            acc[0][7] = fma2(av01.x, b7, acc[0][7]);
            acc[1][0] = fma2(av01.y, b0, acc[1][0]);
            acc[1][1] = fma2(av01.y, b1, acc[1][1]);
            acc[1][2] = fma2(av01.y, b2, acc[1][2]);
            acc[1][3] = fma2(av01.y, b3, acc[1][3]);
            acc[1][4] = fma2(av01.y, b4, acc[1][4]);
            acc[1][5] = fma2(av01.y, b5, acc[1][5]);
            acc[1][6] = fma2(av01.y, b6, acc[1][6]);
            acc[1][7] = fma2(av01.y, b7, acc[1][7]);
            acc[2][0] = fma2(av23.x, b0, acc[2][0]);
            acc[2][1] = fma2(av23.x, b1, acc[2][1]);
            acc[2][2] = fma2(av23.x, b2, acc[2][2]);
            acc[2][3] = fma2(av23.x, b3, acc[2][3]);
            acc[2][4] = fma2(av23.x, b4, acc[2][4]);
            acc[2][5] = fma2(av23.x, b5, acc[2][5]);
            acc[2][6] = fma2(av23.x, b6, acc[2][6]);
            acc[2][7] = fma2(av23.x, b7, acc[2][7]);
            acc[3][0] = fma2(av23.y, b0, acc[3][0]);
            acc[3][1] = fma2(av23.y, b1, acc[3][1]);
            acc[3][2] = fma2(av23.y, b2, acc[3][2]);
            acc[3][3] = fma2(av23.y, b3, acc[3][3]);
            acc[3][4] = fma2(av23.y, b4, acc[3][4]);
            acc[3][5] = fma2(av23.y, b5, acc[3][5]);
            acc[3][6] = fma2(av23.y, b6, acc[3][6]);
            acc[3][7] = fma2(av23.y, b7, acc[3][7]);
        }
        __syncthreads();
        if (kt + 1 < KT) {
            As[lk + 0][lm] = an.x; As[lk + 1][lm] = an.y;
            As[lk + 2][lm] = an.z; As[lk + 3][lm] = an.w;
            Bs[0][tid]  = bn0.x; Bs[1][tid]  = bn0.y; Bs[2][tid]  = bn0.z; Bs[3][tid]  = bn0.w;
            Bs[4][tid]  = bn1.x; Bs[5][tid]  = bn1.y; Bs[6][tid]  = bn1.z; Bs[7][tid]  = bn1.w;
            Bs[8][tid]  = bn2.x; Bs[9][tid]  = bn2.y; Bs[10][tid] = bn2.z; Bs[11][tid] = bn2.w;
            Bs[12][tid] = bn3.x; Bs[13][tid] = bn3.y; Bs[14][tid] = bn3.z; Bs[15][tid] = bn3.w;
            __syncthreads();
        }
    }

    // epilogue: rows ty*8 + (2p, 2p+1), cols ncol0 + tx*8 .. +7
    const int n0 = ncol0 + (tx << 3);
    float4 bs0 = *(const float4*)(bout + n0);
    float4 bs1 = *(const float4*)(bout + n0 + 4);
#pragma unroll
    for (int p = 0; p < 4; ++p) {
        float2 c0 = unpack2(acc[p][0]);
        float2 c1 = unpack2(acc[p][1]);
        float2 c2 = unpack2(acc[p][2]);
        float2 c3 = unpack2(acc[p][3]);
        float2 c4 = unpack2(acc[p][4]);
        float2 c5 = unpack2(acc[p][5]);
        float2 c6 = unpack2(acc[p][6]);
        float2 c7 = unpack2(acc[p][7]);
        int r0 = (ty << 3) + 2 * p;
        float4 lo0 = make_float4(c0.x + bs0.x, c1.x + bs0.y, c2.x + bs0.z, c3.x + bs0.w);
        float4 lo1 = make_float4(c4.x + bs1.x, c5.x + bs1.y, c6.x + bs1.z, c7.x + bs1.w);
        float4 hi0 = make_float4(c0.y + bs0.x, c1.y + bs0.y, c2.y + bs0.z, c3.y + bs0.w);
        float4 hi1 = make_float4(c4.y + bs1.x, c5.y + bs1.y, c6.y + bs1.z, c7.y + bs1.w);
        *(float4*)(out + (size_t)r0 * VV + n0)           = lo0;
        *(float4*)(out + (size_t)r0 * VV + n0 + 4)       = lo1;
        *(float4*)(out + (size_t)(r0 + 1) * VV + n0)     = hi0;
        *(float4*)(out + (size_t)(r0 + 1) * VV + n0 + 4) = hi1;
    }
}

// ---------------- GRU elementwise update -------------------------------------
__global__ void hnew_kernel() {
    int i = blockIdx.x * blockDim.x + threadIdx.x;   // [0, B*H)
    int b = i / HH, u = i % HH;
    const float* gi = g_gi + (size_t)b * G3;
    const float* gh = g_gh + (size_t)b * G3;
    float ir = gi[u], iz = gi[HH + u], in_ = gi[2 * HH + u];
    float hr = gh[u], hz = gh[HH + u], hn  = gh[2 * HH + u];
    float r = 1.0f / (1.0f + expf(-(ir + hr)));
    float z = 1.0f / (1.0f + expf(-(iz + hz)));
    float n = tanhf(in_ + r * hn);
    float h = g_h[i];
    g_h[i] = (1.0f - z) * n + z * h;
}

// ---------------- Gumbel-max categorical sampling (fused, 1 block per row) ---
__global__ __launch_bounds__(256) void sample_kernel(
    const float* __restrict__ logits, unsigned k0, unsigned k1,
    float* __restrict__ ids_out, int t, int write_ids) {
    __shared__ unsigned long long red[256];
    const int b   = blockIdx.x;            // 0..63
    const int tid = threadIdx.x;

    unsigned long long best = 0ull;
    for (int v = tid; v < VV; v += 256) {
        unsigned e = (unsigned)(b * VV + v);
        float val = logits[(size_t)b * VV + v] + gumbel_from_bits(jax_bits32(k0, k1, e));
        unsigned long long p =
            ((unsigned long long)orderf(val) << 32) | (0xFFFFFFFFu - (unsigned)v);
        if (p > best) best = p;
    }
    red[tid] = best;
    __syncthreads();
#pragma unroll
    for (int s = 128; s > 0; s >>= 1) {
        if (tid < s) {
            if (red[tid + s] > red[tid]) red[tid] = red[tid + s];
        }
        __syncthreads();
    }
    if (tid == 0) {
        int sid = (int)(0xFFFFFFFFu - (unsigned)(red[0] & 0xFFFFFFFFull));
        g_sid[b] = sid;
        if (write_ids) ids_out[(size_t)b * TT + t] = (float)sid;
    }
}

// ---------------- launch -----------------------------------------------------
extern "C" void kernel_launch(void* const* d_in, const int* in_sizes, int n_in,
                              void* d_out, int out_size) {
    (void)in_sizes;
    int o = (n_in >= 11) ? 1 : 0;   // optional max_length scalar at slot 1
    const int*   inputs      = (const int*)  d_in[0];
    const float* init_hidden = (const float*)d_in[1 + o];
    const float* att         = (const float*)d_in[2 + o];
    const float* emb         = (const float*)d_in[3 + o];
    const float* W_ih        = (const float*)d_in[4 + o];
    const float* W_hh        = (const float*)d_in[5 + o];
    const float* b_ih        = (const float*)d_in[6 + o];
    const float* b_hh        = (const float*)d_in[7 + o];
    const float* W_out       = (const float*)d_in[8 + o];
    const float* b_out       = (const float*)d_in[9 + o];
    float* out = (float*)d_out;

    const long long TBV = (long long)TT * BB * VV;
    const int has_ids   = ((long long)out_size >= TBV + (long long)BB * TT) ? 1 : 0;
    float* ids_out = out + TBV;

    // per-step PRNG keys: partitionable (fold-like) split of key(42):
    // keys[t] = threefry2x32(key=(0,42), x0=0, x1=t) -> (o0, o1)
    unsigned keys[TT][2];
    for (int t = 0; t < TT; ++t) {
        unsigned a, b;
        tf2x32(0u, 42u, 0u, (unsigned)t, &a, &b);
        keys[t][0] = a; keys[t][1] = b;
    }

    init_kernel<<<(BB * HH) / 256, 256>>>(init_hidden, att);
    for (int t = 0; t < TT; ++t) {
        gates_gemm<<<96, 256>>>(emb, inputs, W_ih, W_hh, b_ih, b_hh, t);
        hnew_kernel<<<(BB * HH) / 256, 256>>>();
        logits_gemm<<<VV / NT, 256>>>(W_out, b_out, out + (size_t)t * BB * VV);
        sample_kernel<<<BB, 256>>>(out + (size_t)t * BB * VV,
                                   keys[t][0], keys[t][1], ids_out, t, has_ids);
    }
}

// round 6
// speedup vs baseline: 1.2733x; 1.2733x over previous
#include <cuda_runtime.h>
#include <cstdint>
#include <cstddef>

// Problem constants
#define BB    64
#define VV    32000
#define EE    512
#define HH    1024
#define G3    3072
#define TT    64
#define DINIT 768
#define DATT  256
#define NT    256          // logits N-tile per CTA
#define SCH   8            // sampling chunks per batch row

// ---------------- scratch (device globals; no allocations allowed) ----------
__device__ float g_h[BB * HH];                 // hidden state (in-place update)
__device__ float g_gi[BB * G3];                // x @ W_ih^T + b_ih
__device__ float g_gh[BB * G3];                // h @ W_hh^T + b_hh
__device__ int   g_sid[BB];                    // sampled ids (feedback)
__device__ unsigned long long g_part[BB][SCH]; // per-chunk argmax partials

// ---------------- f32x2 packed math helpers ---------------------------------
__device__ __forceinline__ unsigned long long pack2(float lo, float hi) {
    unsigned long long r;
    asm("mov.b64 %0, {%1,%2};" : "=l"(r) : "f"(lo), "f"(hi));
    return r;
}
__device__ __forceinline__ unsigned long long fma2(unsigned long long a,
                                                   unsigned long long b,
                                                   unsigned long long c) {
    unsigned long long d;
    asm("fma.rn.f32x2 %0, %1, %2, %3;" : "=l"(d) : "l"(a), "l"(b), "l"(c));
    return d;
}
__device__ __forceinline__ float2 unpack2(unsigned long long v) {
    float2 f;
    asm("mov.b64 {%0,%1}, %2;" : "=f"(f.x), "=f"(f.y) : "l"(v));
    return f;
}

// ---------------- threefry2x32 (exact JAX schedule) --------------------------
__host__ __device__ static inline void tf2x32(unsigned k0, unsigned k1,
                                              unsigned x0, unsigned x1,
                                              unsigned* o0, unsigned* o1) {
    unsigned ks2 = k0 ^ k1 ^ 0x1BD11BDAu;
#define TF_RND(R) { x0 += x1; x1 = (x1 << (R)) | (x1 >> (32 - (R))); x1 ^= x0; }
    x0 += k0; x1 += k1;
    TF_RND(13) TF_RND(15) TF_RND(26) TF_RND(6)
    x0 += k1;  x1 += ks2 + 1u;
    TF_RND(17) TF_RND(29) TF_RND(16) TF_RND(24)
    x0 += ks2; x1 += k0 + 2u;
    TF_RND(13) TF_RND(15) TF_RND(26) TF_RND(6)
    x0 += k0;  x1 += k1 + 3u;
    TF_RND(17) TF_RND(29) TF_RND(16) TF_RND(24)
    x0 += k1;  x1 += ks2 + 4u;
    TF_RND(13) TF_RND(15) TF_RND(26) TF_RND(6)
    x0 += ks2; x1 += k0 + 5u;
#undef TF_RND
    *o0 = x0; *o1 = x1;
}

// JAX partitionable random_bits (32-bit): counter = 64-bit flat index e
// (hi = 0 for our sizes), draw = o0 ^ o1.
__device__ __forceinline__ unsigned jax_bits32(unsigned k0, unsigned k1,
                                               unsigned e) {
    unsigned o0, o1;
    tf2x32(k0, k1, 0u, e, &o0, &o1);
    return o0 ^ o1;
}

// JAX uniform->gumbel
__device__ __forceinline__ float gumbel_from_bits(unsigned bits) {
    float u = __uint_as_float((bits >> 9) | 0x3f800000u) - 1.0f;
    u = u + 1.17549435082228750797e-38f;   // == max(tiny, u0) in fp32
    return -logf(-logf(u));
}

__device__ __forceinline__ unsigned orderf(float f) {
    unsigned u = __float_as_uint(f);
    return (u & 0x80000000u) ? ~u : (u | 0x80000000u);
}

// ---------------- init: h0 = concat(init_hidden, att_embedding) --------------
__global__ void init_kernel(const float* __restrict__ init_hidden,
                            const float* __restrict__ att) {
    int i = blockIdx.x * blockDim.x + threadIdx.x;   // [0, B*H)
    int b = i / HH, u = i % HH;
    g_h[i] = (u < DINIT) ? init_hidden[b * DINIT + u]
                         : att[b * DATT + (u - DINIT)];
}

// ---------------- gates SGEMM: 64x64 tiles (f32x2) ---------------------------
// blocks [0,48)   -> gi = X(gathered emb rows) @ W_ih^T + b_ih
// blocks [48,96)  -> gh = h @ W_hh^T + b_hh
__global__ __launch_bounds__(256) void gates_gemm(
    const float* __restrict__ emb,
    const int*   __restrict__ inputs,
    const float* __restrict__ Wih, const float* __restrict__ Whh,
    const float* __restrict__ bih, const float* __restrict__ bhh,
    int t) {

    __shared__ __align__(16) float As[16][64];
    __shared__ __align__(16) float Bs[16][64];
    __shared__ const float* rowp[64];

    const float* W; const float* bias; float* C;
    int K, ncol0;
    bool gather = false;
    if (blockIdx.x < 48) {
        gather = true; W = Wih; bias = bih; C = g_gi;
        K = EE; ncol0 = blockIdx.x * 64;
    } else {
        W = Whh; bias = bhh; C = g_gh;
        K = HH; ncol0 = (blockIdx.x - 48) * 64;
    }

    const int tid = threadIdx.x;
    if (tid < 64) {
        if (gather) {
            int sid = (t == 0) ? inputs[tid] : g_sid[tid];
            rowp[tid] = emb + (size_t)sid * EE;
        } else {
            rowp[tid] = g_h + (size_t)tid * HH;
        }
    }
    __syncthreads();

    const int lm = tid >> 2;          // row loaded (0..63)
    const int lk = (tid & 3) << 2;    // k offset (0,4,8,12)

    {
        float4 a  = *(const float4*)(rowp[lm] + lk);
        float4 bt = *(const float4*)(W + (size_t)(ncol0 + lm) * K + lk);
        As[lk + 0][lm] = a.x;  As[lk + 1][lm] = a.y;
        As[lk + 2][lm] = a.z;  As[lk + 3][lm] = a.w;
        Bs[lk + 0][lm] = bt.x; Bs[lk + 1][lm] = bt.y;
        Bs[lk + 2][lm] = bt.z; Bs[lk + 3][lm] = bt.w;
    }
    __syncthreads();

    const int tx = tid & 15;   // cols ncol0 + tx*4 .. +3
    const int ty = tid >> 4;   // rows ty*4 .. +3

    unsigned long long acc[2][4];
#pragma unroll
    for (int p = 0; p < 2; ++p)
#pragma unroll
        for (int n = 0; n < 4; ++n) acc[p][n] = 0ull;

    const int KT = K >> 4;
    for (int kt = 0; kt < KT; ++kt) {
        float4 an, bn;
        if (kt + 1 < KT) {
            int k0 = (kt + 1) << 4;
            an = *(const float4*)(rowp[lm] + k0 + lk);
            bn = *(const float4*)(W + (size_t)(ncol0 + lm) * K + k0 + lk);
        }
#pragma unroll
        for (int kk = 0; kk < 16; ++kk) {
            ulonglong2 av = *(const ulonglong2*)&As[kk][ty << 2];
            float4     bv = *(const float4*)&Bs[kk][tx << 2];
            unsigned long long b0 = pack2(bv.x, bv.x);
            unsigned long long b1 = pack2(bv.y, bv.y);
            unsigned long long b2 = pack2(bv.z, bv.z);
            unsigned long long b3 = pack2(bv.w, bv.w);
            acc[0][0] = fma2(av.x, b0, acc[0][0]);
            acc[0][1] = fma2(av.x, b1, acc[0][1]);
            acc[0][2] = fma2(av.x, b2, acc[0][2]);
            acc[0][3] = fma2(av.x, b3, acc[0][3]);
            acc[1][0] = fma2(av.y, b0, acc[1][0]);
            acc[1][1] = fma2(av.y, b1, acc[1][1]);
            acc[1][2] = fma2(av.y, b2, acc[1][2]);
            acc[1][3] = fma2(av.y, b3, acc[1][3]);
        }
        __syncthreads();
        if (kt + 1 < KT) {
            As[lk + 0][lm] = an.x; As[lk + 1][lm] = an.y;
            As[lk + 2][lm] = an.z; As[lk + 3][lm] = an.w;
            Bs[lk + 0][lm] = bn.x; Bs[lk + 1][lm] = bn.y;
            Bs[lk + 2][lm] = bn.z; Bs[lk + 3][lm] = bn.w;
            __syncthreads();
        }
    }

    const int m0 = ty << 2;
    const int n0 = ncol0 + (tx << 2);
    float4 bsv = *(const float4*)(bias + n0);
#pragma unroll
    for (int p = 0; p < 2; ++p) {
        float2 c0 = unpack2(acc[p][0]);
        float2 c1 = unpack2(acc[p][1]);
        float2 c2 = unpack2(acc[p][2]);
        float2 c3 = unpack2(acc[p][3]);
        int r0 = m0 + 2 * p;
        float4 w0 = make_float4(c0.x + bsv.x, c1.x + bsv.y, c2.x + bsv.z, c3.x + bsv.w);
        float4 w1 = make_float4(c0.y + bsv.x, c1.y + bsv.y, c2.y + bsv.z, c3.y + bsv.w);
        *(float4*)(C + (size_t)r0 * G3 + n0)       = w0;
        *(float4*)(C + (size_t)(r0 + 1) * G3 + n0) = w1;
    }
}

// ---------------- logits SGEMM: 64x256 CTA tile, 8x8 per thread --------------
// grid = 125, block = 256. C = h @ W_out^T + b_out
// N mapping per thread: cols {tx*4..+3} and {128+tx*4..+3} (16B-stride lanes,
// conflict-free LDS.128 on B).
__global__ __launch_bounds__(256) void logits_gemm(
    const float* __restrict__ Wout, const float* __restrict__ bout,
    float* __restrict__ out) {

    __shared__ __align__(16) float As[16][64];
    __shared__ __align__(16) float Bs[16][NT];

    const int tid   = threadIdx.x;
    const int ncol0 = blockIdx.x * NT;

    const int lm = tid >> 2;          // A row loaded (0..63)
    const int lk = (tid & 3) << 2;    // A k offset (0,4,8,12)
    const float* Wrow = Wout + (size_t)(ncol0 + tid) * HH;   // B row n = tid

    // first tile
    {
        float4 a = *(const float4*)(g_h + (size_t)lm * HH + lk);
        As[lk + 0][lm] = a.x; As[lk + 1][lm] = a.y;
        As[lk + 2][lm] = a.z; As[lk + 3][lm] = a.w;
#pragma unroll
        for (int j = 0; j < 4; ++j) {
            float4 b = *(const float4*)(Wrow + 4 * j);
            Bs[4 * j + 0][tid] = b.x; Bs[4 * j + 1][tid] = b.y;
            Bs[4 * j + 2][tid] = b.z; Bs[4 * j + 3][tid] = b.w;
        }
    }
    __syncthreads();

    const int tx = tid & 31;   // n-groups: cols tx*4..+3 and 128+tx*4..+3
    const int ty = tid >> 5;   // m-group: rows ty*8 .. +7 (4 packed pairs)

    unsigned long long acc[4][8];
#pragma unroll
    for (int p = 0; p < 4; ++p)
#pragma unroll
        for (int n = 0; n < 8; ++n) acc[p][n] = 0ull;

    const int KT = HH >> 4;    // 64 k-tiles
    for (int kt = 0; kt < KT; ++kt) {
        float4 an, bn0, bn1, bn2, bn3;
        if (kt + 1 < KT) {
            int k0 = (kt + 1) << 4;
            an  = *(const float4*)(g_h + (size_t)lm * HH + k0 + lk);
            bn0 = *(const float4*)(Wrow + k0 + 0);
            bn1 = *(const float4*)(Wrow + k0 + 4);
            bn2 = *(const float4*)(Wrow + k0 + 8);
            bn3 = *(const float4*)(Wrow + k0 + 12);
        }
#pragma unroll
        for (int kk = 0; kk < 16; ++kk) {
            ulonglong2 av01 = *(const ulonglong2*)&As[kk][ty << 3];
            ulonglong2 av23 = *(const ulonglong2*)&As[kk][(ty << 3) + 4];
            float4 bv0 = *(const float4*)&Bs[kk][tx << 2];          // cols tx*4..+3
            float4 bv1 = *(const float4*)&Bs[kk][128 + (tx << 2)];  // cols 128+tx*4..+3
            unsigned long long b0 = pack2(bv0.x, bv0.x);
            unsigned long long b1 = pack2(bv0.y, bv0.y);
            unsigned long long b2 = pack2(bv0.z, bv0.z);
            unsigned long long b3 = pack2(bv0.w, bv0.w);
            unsigned long long b4 = pack2(bv1.x, bv1.x);
            unsigned long long b5 = pack2(bv1.y, bv1.y);
            unsigned long long b6 = pack2(bv1.z, bv1.z);
            unsigned long long b7 = pack2(bv1.w, bv1.w);
            acc[0][0] = fma2(av01.x, b0, acc[0][0]);
            acc[0][1] = fma2(av01.x, b1, acc[0][1]);
            acc[0][2] = fma2(av01.x, b2, acc[0][2]);
            acc[0][3] = fma2(av01.x, b3, acc[0][3]);
            acc[0][4] = fma2(av01.x, b4, acc[0][4]);
            acc[0][5] = fma2(av01.x, b5, acc[0][5]);
            acc[0][6] = fma2(av01.x, b6, acc[0][6]);
            acc[0][7] = fma2(av01.x, b7, acc[0][7]);
            acc[1][0] = fma2(av01.y, b0, acc[1][0]);
            acc[1][1] = fma2(av01.y, b1, acc[1][1]);
            acc[1][2] = fma2(av01.y, b2, acc[1][2]);
            acc[1][3] = fma2(av01.y, b3, acc[1][3]);
            acc[1][4] = fma2(av01.y, b4, acc[1][4]);
            acc[1][5] = fma2(av01.y, b5, acc[1][5]);
            acc[1][6] = fma2(av01.y, b6, acc[1][6]);
            acc[1][7] = fma2(av01.y, b7, acc[1][7]);
            acc[2][0] = fma2(av23.x, b0, acc[2][0]);
            acc[2][1] = fma2(av23.x, b1, acc[2][1]);
            acc[2][2] = fma2(av23.x, b2, acc[2][2]);
            acc[2][3] = fma2(av23.x, b3, acc[2][3]);
            acc[2][4] = fma2(av23.x, b4, acc[2][4]);
            acc[2][5] = fma2(av23.x, b5, acc[2][5]);
            acc[2][6] = fma2(av23.x, b6, acc[2][6]);
            acc[2][7] = fma2(av23.x, b7, acc[2][7]);
            acc[3][0] = fma2(av23.y, b0, acc[3][0]);
            acc[3][1] = fma2(av23.y, b1, acc[3][1]);
            acc[3][2] = fma2(av23.y, b2, acc[3][2]);
            acc[3][3] = fma2(av23.y, b3, acc[3][3]);
            acc[3][4] = fma2(av23.y, b4, acc[3][4]);
            acc[3][5] = fma2(av23.y, b5, acc[3][5]);
            acc[3][6] = fma2(av23.y, b6, acc[3][6]);
            acc[3][7] = fma2(av23.y, b7, acc[3][7]);
        }
        __syncthreads();
        if (kt + 1 < KT) {
            As[lk + 0][lm] = an.x; As[lk + 1][lm] = an.y;
            As[lk + 2][lm] = an.z; As[lk + 3][lm] = an.w;
            Bs[0][tid]  = bn0.x; Bs[1][tid]  = bn0.y; Bs[2][tid]  = bn0.z; Bs[3][tid]  = bn0.w;
            Bs[4][tid]  = bn1.x; Bs[5][tid]  = bn1.y; Bs[6][tid]  = bn1.z; Bs[7][tid]  = bn1.w;
            Bs[8][tid]  = bn2.x; Bs[9][tid]  = bn2.y; Bs[10][tid] = bn2.z; Bs[11][tid] = bn2.w;
            Bs[12][tid] = bn3.x; Bs[13][tid] = bn3.y; Bs[14][tid] = bn3.z; Bs[15][tid] = bn3.w;
            __syncthreads();
        }
    }

    // epilogue: rows ty*8 + (2p, 2p+1), col groups {n0a..+3} and {n0b..+3}
    const int n0a = ncol0 + (tx << 2);
    const int n0b = n0a + 128;
    float4 bs0 = *(const float4*)(bout + n0a);
    float4 bs1 = *(const float4*)(bout + n0b);
#pragma unroll
    for (int p = 0; p < 4; ++p) {
        float2 c0 = unpack2(acc[p][0]);
        float2 c1 = unpack2(acc[p][1]);
        float2 c2 = unpack2(acc[p][2]);
        float2 c3 = unpack2(acc[p][3]);
        float2 c4 = unpack2(acc[p][4]);
        float2 c5 = unpack2(acc[p][5]);
        float2 c6 = unpack2(acc[p][6]);
        float2 c7 = unpack2(acc[p][7]);
        int r0 = (ty << 3) + 2 * p;
        float4 lo0 = make_float4(c0.x + bs0.x, c1.x + bs0.y, c2.x + bs0.z, c3.x + bs0.w);
        float4 lo1 = make_float4(c4.x + bs1.x, c5.x + bs1.y, c6.x + bs1.z, c7.x + bs1.w);
        float4 hi0 = make_float4(c0.y + bs0.x, c1.y + bs0.y, c2.y + bs0.z, c3.y + bs0.w);
        float4 hi1 = make_float4(c4.y + bs1.x, c5.y + bs1.y, c6.y + bs1.z, c7.y + bs1.w);
        *(float4*)(out + (size_t)r0 * VV + n0a)       = lo0;
        *(float4*)(out + (size_t)r0 * VV + n0b)       = lo1;
        *(float4*)(out + (size_t)(r0 + 1) * VV + n0a) = hi0;
        *(float4*)(out + (size_t)(r0 + 1) * VV + n0b) = hi1;
    }
}

// ---------------- GRU elementwise update -------------------------------------
__global__ void hnew_kernel() {
    int i = blockIdx.x * blockDim.x + threadIdx.x;   // [0, B*H)
    int b = i / HH, u = i % HH;
    const float* gi = g_gi + (size_t)b * G3;
    const float* gh = g_gh + (size_t)b * G3;
    float ir = gi[u], iz = gi[HH + u], in_ = gi[2 * HH + u];
    float hr = gh[u], hz = gh[HH + u], hn  = gh[2 * HH + u];
    float r = 1.0f / (1.0f + expf(-(ir + hr)));
    float z = 1.0f / (1.0f + expf(-(iz + hz)));
    float n = tanhf(in_ + r * hn);
    float h = g_h[i];
    g_h[i] = (1.0f - z) * n + z * h;
}

// ---------------- Gumbel-max partial argmax (grid = (SCH, BB)) ---------------
__global__ __launch_bounds__(256) void sample_kernel(
    const float* __restrict__ logits, unsigned k0, unsigned k1) {
    __shared__ unsigned long long red[256];
    const int b   = blockIdx.y;                 // 0..63
    const int c   = blockIdx.x;                 // 0..SCH-1
    const int v0  = c * (VV / SCH);             // 4000-wide chunks
    const int tid = threadIdx.x;

    unsigned long long best = 0ull;
    for (int i = tid; i < VV / SCH; i += 256) {
        int v = v0 + i;
        unsigned e = (unsigned)(b * VV + v);
        float val = logits[(size_t)b * VV + v] + gumbel_from_bits(jax_bits32(k0, k1, e));
        unsigned long long p =
            ((unsigned long long)orderf(val) << 32) | (0xFFFFFFFFu - (unsigned)v);
        if (p > best) best = p;
    }
    red[tid] = best;
    __syncthreads();
#pragma unroll
    for (int s = 128; s > 0; s >>= 1) {
        if (tid < s) {
            if (red[tid + s] > red[tid]) red[tid] = red[tid + s];
        }
        __syncthreads();
    }
    if (tid == 0) g_part[b][c] = red[0];
}

// ---------------- final reduce: write g_sid + ids_out ------------------------
__global__ void record_kernel(float* __restrict__ ids_out, int t, int write_ids) {
    int b = threadIdx.x;
    if (b < BB) {
        unsigned long long best = 0ull;
#pragma unroll
        for (int c = 0; c < SCH; ++c) {
            unsigned long long p = g_part[b][c];
            if (p > best) best = p;
        }
        int sid = (int)(0xFFFFFFFFu - (unsigned)(best & 0xFFFFFFFFull));
        g_sid[b] = sid;
        if (write_ids) ids_out[(size_t)b * TT + t] = (float)sid;
    }
}

// ---------------- launch -----------------------------------------------------
extern "C" void kernel_launch(void* const* d_in, const int* in_sizes, int n_in,
                              void* d_out, int out_size) {
    (void)in_sizes;
    int o = (n_in >= 11) ? 1 : 0;   // optional max_length scalar at slot 1
    const int*   inputs      = (const int*)  d_in[0];
    const float* init_hidden = (const float*)d_in[1 + o];
    const float* att         = (const float*)d_in[2 + o];
    const float* emb         = (const float*)d_in[3 + o];
    const float* W_ih        = (const float*)d_in[4 + o];
    const float* W_hh        = (const float*)d_in[5 + o];
    const float* b_ih        = (const float*)d_in[6 + o];
    const float* b_hh        = (const float*)d_in[7 + o];
    const float* W_out       = (const float*)d_in[8 + o];
    const float* b_out       = (const float*)d_in[9 + o];
    float* out = (float*)d_out;

    const long long TBV = (long long)TT * BB * VV;
    const int has_ids   = ((long long)out_size >= TBV + (long long)BB * TT) ? 1 : 0;
    float* ids_out = out + TBV;

    // per-step PRNG keys: partitionable (fold-like) split of key(42):
    // keys[t] = threefry2x32(key=(0,42), x0=0, x1=t) -> (o0, o1)
    unsigned keys[TT][2];
    for (int t = 0; t < TT; ++t) {
        unsigned a, b;
        tf2x32(0u, 42u, 0u, (unsigned)t, &a, &b);
        keys[t][0] = a; keys[t][1] = b;
    }

    init_kernel<<<(BB * HH) / 256, 256>>>(init_hidden, att);
    for (int t = 0; t < TT; ++t) {
        gates_gemm<<<96, 256>>>(emb, inputs, W_ih, W_hh, b_ih, b_hh, t);
        hnew_kernel<<<(BB * HH) / 256, 256>>>();
        logits_gemm<<<VV / NT, 256>>>(W_out, b_out, out + (size_t)t * BB * VV);
        sample_kernel<<<dim3(SCH, BB), 256>>>(out + (size_t)t * BB * VV,
                                              keys[t][0], keys[t][1]);
        record_kernel<<<1, 64>>>(ids_out, t, has_ids);
    }
}

// round 9
// speedup vs baseline: 1.7972x; 1.4115x over previous
#include <cuda_runtime.h>
#include <cuda_fp16.h>
#include <cstdint>
#include <cstddef>

// Problem constants
#define BB    64
#define VV    32000
#define EE    512
#define HH    1024
#define G3    3072
#define TT    64
#define DINIT 768
#define DATT  256
#define SCH   8            // sampling chunks per batch row

// logits HMMA tiling
#define KCH   32           // K-chunk
#define NKC   (HH / KCH)   // 32 chunks
#define WP    40           // SMEM row pitch in fp16 (80B, conflict-free LDSM)

// ---------------- scratch (device globals; no allocations allowed) ----------
__device__ float g_h[BB * HH];                 // hidden state (in-place update)
__device__ float g_gi[BB * G3];                // x @ W_ih^T + b_ih
__device__ float g_gh[BB * G3];                // h @ W_hh^T + b_hh
__device__ int   g_sid[BB];                    // sampled ids (feedback)
__device__ unsigned long long g_part[BB][SCH]; // per-chunk argmax partials

// ---------------- f32x2 packed math helpers (gates gemm) --------------------
__device__ __forceinline__ unsigned long long pack2(float lo, float hi) {
    unsigned long long r;
    asm("mov.b64 %0, {%1,%2};" : "=l"(r) : "f"(lo), "f"(hi));
    return r;
}
__device__ __forceinline__ unsigned long long fma2(unsigned long long a,
                                                   unsigned long long b,
                                                   unsigned long long c) {
    unsigned long long d;
    asm("fma.rn.f32x2 %0, %1, %2, %3;" : "=l"(d) : "l"(a), "l"(b), "l"(c));
    return d;
}
__device__ __forceinline__ float2 unpack2(unsigned long long v) {
    float2 f;
    asm("mov.b64 {%0,%1}, %2;" : "=f"(f.x), "=f"(f.y) : "l"(v));
    return f;
}

// ---------------- HMMA helpers ------------------------------------------------
__device__ __forceinline__ uint32_t smem_u32(const void* p) {
    uint32_t a;
    asm("{ .reg .u64 t; cvta.to.shared.u64 t, %1; cvt.u32.u64 %0, t; }"
        : "=r"(a) : "l"(p));
    return a;
}
__device__ __forceinline__ void ldsm4(uint32_t* r, uint32_t addr) {
    asm volatile("ldmatrix.sync.aligned.m8n8.x4.shared.b16 {%0,%1,%2,%3}, [%4];"
                 : "=r"(r[0]), "=r"(r[1]), "=r"(r[2]), "=r"(r[3]) : "r"(addr));
}
__device__ __forceinline__ void mma16816(float* d, const uint32_t* a,
                                         const uint32_t* b) {
    asm volatile(
        "mma.sync.aligned.m16n8k16.row.col.f32.f16.f16.f32 "
        "{%0,%1,%2,%3}, {%4,%5,%6,%7}, {%8,%9}, {%0,%1,%2,%3};"
        : "+f"(d[0]), "+f"(d[1]), "+f"(d[2]), "+f"(d[3])
        : "r"(a[0]), "r"(a[1]), "r"(a[2]), "r"(a[3]), "r"(b[0]), "r"(b[1]));
}
__device__ __forceinline__ uint32_t pack_lohi(unsigned short lo,
                                              unsigned short hi) {
    return (uint32_t)lo | ((uint32_t)hi << 16);
}
__device__ __forceinline__ void split2(float x, unsigned short& s1,
                                       unsigned short& s2) {
    __half h1 = __float2half_rn(x);
    float f1 = __half2float(h1);
    __half h2 = __float2half_rn(x - f1);
    s1 = __half_as_ushort(h1);
    s2 = __half_as_ushort(h2);
}

// ---------------- threefry2x32 (exact JAX schedule) --------------------------
__host__ __device__ static inline void tf2x32(unsigned k0, unsigned k1,
                                              unsigned x0, unsigned x1,
                                              unsigned* o0, unsigned* o1) {
    unsigned ks2 = k0 ^ k1 ^ 0x1BD11BDAu;
#define TF_RND(R) { x0 += x1; x1 = (x1 << (R)) | (x1 >> (32 - (R))); x1 ^= x0; }
    x0 += k0; x1 += k1;
    TF_RND(13) TF_RND(15) TF_RND(26) TF_RND(6)
    x0 += k1;  x1 += ks2 + 1u;
    TF_RND(17) TF_RND(29) TF_RND(16) TF_RND(24)
    x0 += ks2; x1 += k0 + 2u;
    TF_RND(13) TF_RND(15) TF_RND(26) TF_RND(6)
    x0 += k0;  x1 += k1 + 3u;
    TF_RND(17) TF_RND(29) TF_RND(16) TF_RND(24)
    x0 += k1;  x1 += ks2 + 4u;
    TF_RND(13) TF_RND(15) TF_RND(26) TF_RND(6)
    x0 += ks2; x1 += k0 + 5u;
#undef TF_RND
    *o0 = x0; *o1 = x1;
}

__device__ __forceinline__ unsigned jax_bits32(unsigned k0, unsigned k1,
                                               unsigned e) {
    unsigned o0, o1;
    tf2x32(k0, k1, 0u, e, &o0, &o1);
    return o0 ^ o1;
}

__device__ __forceinline__ float gumbel_from_bits(unsigned bits) {
    float u = __uint_as_float((bits >> 9) | 0x3f800000u) - 1.0f;
    u = u + 1.17549435082228750797e-38f;   // == max(tiny, u0) in fp32
    return -logf(-logf(u));
}

__device__ __forceinline__ unsigned orderf(float f) {
    unsigned u = __float_as_uint(f);
    return (u & 0x80000000u) ? ~u : (u | 0x80000000u);
}

// ---------------- init: h0 = concat(init_hidden, att_embedding) --------------
__global__ void init_kernel(const float* __restrict__ init_hidden,
                            const float* __restrict__ att) {
    int i = blockIdx.x * blockDim.x + threadIdx.x;   // [0, B*H)
    int b = i / HH, u = i % HH;
    g_h[i] = (u < DINIT) ? init_hidden[b * DINIT + u]
                         : att[b * DATT + (u - DINIT)];
}

// ---------------- gates SGEMM: 64x64 tiles (f32x2) ---------------------------
__global__ __launch_bounds__(256) void gates_gemm(
    const float* __restrict__ emb,
    const int*   __restrict__ inputs,
    const float* __restrict__ Wih, const float* __restrict__ Whh,
    const float* __restrict__ bih, const float* __restrict__ bhh,
    int t) {

    __shared__ __align__(16) float As[16][64];
    __shared__ __align__(16) float Bs[16][64];
    __shared__ const float* rowp[64];

    const float* W; const float* bias; float* C;
    int K, ncol0;
    bool gather = false;
    if (blockIdx.x < 48) {
        gather = true; W = Wih; bias = bih; C = g_gi;
        K = EE; ncol0 = blockIdx.x * 64;
    } else {
        W = Whh; bias = bhh; C = g_gh;
        K = HH; ncol0 = (blockIdx.x - 48) * 64;
    }

    const int tid = threadIdx.x;
    if (tid < 64) {
        if (gather) {
            int sid = (t == 0) ? inputs[tid] : g_sid[tid];
            rowp[tid] = emb + (size_t)sid * EE;
        } else {
            rowp[tid] = g_h + (size_t)tid * HH;
        }
    }
    __syncthreads();

    const int lm = tid >> 2;
    const int lk = (tid & 3) << 2;

    {
        float4 a  = *(const float4*)(rowp[lm] + lk);
        float4 bt = *(const float4*)(W + (size_t)(ncol0 + lm) * K + lk);
        As[lk + 0][lm] = a.x;  As[lk + 1][lm] = a.y;
        As[lk + 2][lm] = a.z;  As[lk + 3][lm] = a.w;
        Bs[lk + 0][lm] = bt.x; Bs[lk + 1][lm] = bt.y;
        Bs[lk + 2][lm] = bt.z; Bs[lk + 3][lm] = bt.w;
    }
    __syncthreads();

    const int tx = tid & 15;
    const int ty = tid >> 4;

    unsigned long long acc[2][4];
#pragma unroll
    for (int p = 0; p < 2; ++p)
#pragma unroll
        for (int n = 0; n < 4; ++n) acc[p][n] = 0ull;

    const int KT = K >> 4;
    for (int kt = 0; kt < KT; ++kt) {
        float4 an, bn;
        if (kt + 1 < KT) {
            int k0 = (kt + 1) << 4;
            an = *(const float4*)(rowp[lm] + k0 + lk);
            bn = *(const float4*)(W + (size_t)(ncol0 + lm) * K + k0 + lk);
        }
#pragma unroll
        for (int kk = 0; kk < 16; ++kk) {
            ulonglong2 av = *(const ulonglong2*)&As[kk][ty << 2];
            float4     bv = *(const float4*)&Bs[kk][tx << 2];
            unsigned long long b0 = pack2(bv.x, bv.x);
            unsigned long long b1 = pack2(bv.y, bv.y);
            unsigned long long b2 = pack2(bv.z, bv.z);
            unsigned long long b3 = pack2(bv.w, bv.w);
            acc[0][0] = fma2(av.x, b0, acc[0][0]);
            acc[0][1] = fma2(av.x, b1, acc[0][1]);
            acc[0][2] = fma2(av.x, b2, acc[0][2]);
            acc[0][3] = fma2(av.x, b3, acc[0][3]);
            acc[1][0] = fma2(av.y, b0, acc[1][0]);
            acc[1][1] = fma2(av.y, b1, acc[1][1]);
            acc[1][2] = fma2(av.y, b2, acc[1][2]);
            acc[1][3] = fma2(av.y, b3, acc[1][3]);
        }
        __syncthreads();
        if (kt + 1 < KT) {
            As[lk + 0][lm] = an.x; As[lk + 1][lm] = an.y;
            As[lk + 2][lm] = an.z; As[lk + 3][lm] = an.w;
            Bs[lk + 0][lm] = bn.x; Bs[lk + 1][lm] = bn.y;
            Bs[lk + 2][lm] = bn.z; Bs[lk + 3][lm] = bn.w;
            __syncthreads();
        }
    }

    const int m0 = ty << 2;
    const int n0 = ncol0 + (tx << 2);
    float4 bsv = *(const float4*)(bias + n0);
#pragma unroll
    for (int p = 0; p < 2; ++p) {
        float2 c0 = unpack2(acc[p][0]);
        float2 c1 = unpack2(acc[p][1]);
        float2 c2 = unpack2(acc[p][2]);
        float2 c3 = unpack2(acc[p][3]);
        int r0 = m0 + 2 * p;
        float4 w0 = make_float4(c0.x + bsv.x, c1.x + bsv.y, c2.x + bsv.z, c3.x + bsv.w);
        float4 w1 = make_float4(c0.y + bsv.x, c1.y + bsv.y, c2.y + bsv.z, c3.y + bsv.w);
        *(float4*)(C + (size_t)r0 * G3 + n0)       = w0;
        *(float4*)(C + (size_t)(r0 + 1) * G3 + n0) = w1;
    }
}

// ---------------- logits via HMMA (mma.sync fp16 3-term split) ---------------
// C[b, v] = h[b,:] @ W_out[v,:]^T + b_out[v]
// CTA: M=64 (batch) x N=128 (vocab tile), grid = VV/128 = 250, 8 warps.
// Split: h = h1+h2, W = w1+w2 (fp16); acc += h1w1 + h2w1 + h1w2 (fp32).
__global__ __launch_bounds__(256) void logits_hmma(
    const float* __restrict__ Wout, const float* __restrict__ bout,
    float* __restrict__ out) {

    __shared__ __align__(16) unsigned short sH1[64 * WP];
    __shared__ __align__(16) unsigned short sH2[64 * WP];
    __shared__ __align__(16) unsigned short sW1[128 * WP];
    __shared__ __align__(16) unsigned short sW2[128 * WP];

    const int tid = threadIdx.x;
    const int wid = tid >> 5, lid = tid & 31;
    const int v0 = blockIdx.x * 128;

    // global load mapping (per chunk of 32 k)
    const int wrow = tid >> 1, wk = (tid & 1) << 4;   // W: 128 rows x 32 k
    const int hrow = tid >> 2, hk = (tid & 3) << 3;   // h: 64 rows x 32 k
    const float* wptr = Wout + (size_t)(v0 + wrow) * HH + wk;
    const float* hptr = g_h + (size_t)hrow * HH + hk;

    float4 wre[4], hre[2];
#pragma unroll
    for (int j = 0; j < 4; ++j) wre[j] = *(const float4*)(wptr + 4 * j);
#pragma unroll
    for (int j = 0; j < 2; ++j) hre[j] = *(const float4*)(hptr + 4 * j);

    const int m0 = (wid & 1) << 5;    // batch offset of warp tile
    const int n0 = (wid >> 1) << 5;   // vocab offset within CTA tile

    float acc[2][4][4];
#pragma unroll
    for (int mm = 0; mm < 2; ++mm)
#pragma unroll
        for (int nn = 0; nn < 4; ++nn)
#pragma unroll
            for (int q = 0; q < 4; ++q) acc[mm][nn][q] = 0.0f;

    const uint32_t aH1 = smem_u32(sH1), aH2 = smem_u32(sH2);
    const uint32_t aW1 = smem_u32(sW1), aW2 = smem_u32(sW2);

    const int lj = lid >> 3, lr = lid & 7;   // ldmatrix lane decomposition

    for (int c = 0; c < NKC; ++c) {
        // ---- convert + store W chunk (2 fp16 levels) ----
        {
            unsigned short s1[16], s2[16];
            const float* xs = (const float*)wre;
#pragma unroll
            for (int j = 0; j < 16; ++j) split2(xs[j], s1[j], s2[j]);
            uint32_t* d1 = (uint32_t*)&sW1[wrow * WP + wk];
            uint32_t* d2 = (uint32_t*)&sW2[wrow * WP + wk];
#pragma unroll
            for (int j = 0; j < 8; ++j) {
                d1[j] = pack_lohi(s1[2 * j], s1[2 * j + 1]);
                d2[j] = pack_lohi(s2[2 * j], s2[2 * j + 1]);
            }
        }
        // ---- convert + store h chunk ----
        {
            unsigned short s1[8], s2[8];
            const float* xs = (const float*)hre;
#pragma unroll
            for (int j = 0; j < 8; ++j) split2(xs[j], s1[j], s2[j]);
            uint32_t* d1 = (uint32_t*)&sH1[hrow * WP + hk];
            uint32_t* d2 = (uint32_t*)&sH2[hrow * WP + hk];
#pragma unroll
            for (int j = 0; j < 4; ++j) {
                d1[j] = pack_lohi(s1[2 * j], s1[2 * j + 1]);
                d2[j] = pack_lohi(s2[2 * j], s2[2 * j + 1]);
            }
        }
        __syncthreads();

        // prefetch next chunk (overlaps with MMA)
        if (c + 1 < NKC) {
            const float* wn = wptr + (c + 1) * KCH;
            const float* hn = hptr + (c + 1) * KCH;
#pragma unroll
            for (int j = 0; j < 4; ++j) wre[j] = *(const float4*)(wn + 4 * j);
#pragma unroll
            for (int j = 0; j < 2; ++j) hre[j] = *(const float4*)(hn + 4 * j);
        }

#pragma unroll
        for (int ks = 0; ks < 2; ++ks) {
            const int kb = ks << 4;

            // A fragments (h): 2 m16k16 frags per level
            uint32_t a1[2][4], a2[2][4];
#pragma unroll
            for (int mm = 0; mm < 2; ++mm) {
                int row = m0 + (mm << 4) + ((lj & 1) << 3) + lr;
                int col = kb + ((lj >> 1) << 3);
                uint32_t off = (uint32_t)(row * WP + col) * 2;
                ldsm4(a1[mm], aH1 + off);
                ldsm4(a2[mm], aH2 + off);
            }
            // B fragments (W): 4 n8k16 frags per level (2 LDSM.x4 each)
            uint32_t b1[4][2], b2[4][2];
#pragma unroll
            for (int p = 0; p < 2; ++p) {
                int row = n0 + (p << 4) + ((lj >> 1) << 3) + lr;
                int col = kb + ((lj & 1) << 3);
                uint32_t off = (uint32_t)(row * WP + col) * 2;
                uint32_t t[4];
                ldsm4(t, aW1 + off);
                b1[2 * p][0] = t[0]; b1[2 * p][1] = t[1];
                b1[2 * p + 1][0] = t[2]; b1[2 * p + 1][1] = t[3];
                ldsm4(t, aW2 + off);
                b2[2 * p][0] = t[0]; b2[2 * p][1] = t[1];
                b2[2 * p + 1][0] = t[2]; b2[2 * p + 1][1] = t[3];
            }

            // 3 split terms: h1w1 + h2w1 + h1w2
#pragma unroll
            for (int mm = 0; mm < 2; ++mm)
#pragma unroll
                for (int nn = 0; nn < 4; ++nn) {
                    mma16816(acc[mm][nn], a1[mm], b1[nn]);
                    mma16816(acc[mm][nn], a2[mm], b1[nn]);
                    mma16816(acc[mm][nn], a1[mm], b2[nn]);
                }
        }
        __syncthreads();
    }

    // ---- epilogue: acc rows = batch, cols = vocab; add bias, write ----
#pragma unroll
    for (int nn = 0; nn < 4; ++nn) {
        int v = v0 + n0 + (nn << 3) + ((lid & 3) << 1);
        float2 bias = *(const float2*)(bout + v);
#pragma unroll
        for (int mm = 0; mm < 2; ++mm) {
            int b0i = m0 + (mm << 4) + (lid >> 2);
            float2 lo = make_float2(acc[mm][nn][0] + bias.x,
                                    acc[mm][nn][1] + bias.y);
            float2 hi = make_float2(acc[mm][nn][2] + bias.x,
                                    acc[mm][nn][3] + bias.y);
            *(float2*)(out + (size_t)b0i * VV + v)       = lo;
            *(float2*)(out + (size_t)(b0i + 8) * VV + v) = hi;
        }
    }
}

// ---------------- GRU elementwise update -------------------------------------
__global__ void hnew_kernel() {
    int i = blockIdx.x * blockDim.x + threadIdx.x;   // [0, B*H)
    int b = i / HH, u = i % HH;
    const float* gi = g_gi + (size_t)b * G3;
    const float* gh = g_gh + (size_t)b * G3;
    float ir = gi[u], iz = gi[HH + u], in_ = gi[2 * HH + u];
    float hr = gh[u], hz = gh[HH + u], hn  = gh[2 * HH + u];
    float r = 1.0f / (1.0f + expf(-(ir + hr)));
    float z = 1.0f / (1.0f + expf(-(iz + hz)));
    float n = tanhf(in_ + r * hn);
    float h = g_h[i];
    g_h[i] = (1.0f - z) * n + z * h;
}

// ---------------- Gumbel-max partial argmax (grid = (SCH, BB)) ---------------
__global__ __launch_bounds__(256) void sample_kernel(
    const float* __restrict__ logits, unsigned k0, unsigned k1) {
    __shared__ unsigned long long red[256];
    const int b   = blockIdx.y;
    const int c   = blockIdx.x;
    const int v0  = c * (VV / SCH);
    const int tid = threadIdx.x;

    unsigned long long best = 0ull;
    for (int i = tid; i < VV / SCH; i += 256) {
        int v = v0 + i;
        unsigned e = (unsigned)(b * VV + v);
        float val = logits[(size_t)b * VV + v] + gumbel_from_bits(jax_bits32(k0, k1, e));
        unsigned long long p =
            ((unsigned long long)orderf(val) << 32) | (0xFFFFFFFFu - (unsigned)v);
        if (p > best) best = p;
    }
    red[tid] = best;
    __syncthreads();
#pragma unroll
    for (int s = 128; s > 0; s >>= 1) {
        if (tid < s) {
            if (red[tid + s] > red[tid]) red[tid] = red[tid + s];
        }
        __syncthreads();
    }
    if (tid == 0) g_part[b][c] = red[0];
}

// ---------------- final reduce: write g_sid + ids_out ------------------------
__global__ void record_kernel(float* __restrict__ ids_out, int t, int write_ids) {
    int b = threadIdx.x;
    if (b < BB) {
        unsigned long long best = 0ull;
#pragma unroll
        for (int c = 0; c < SCH; ++c) {
            unsigned long long p = g_part[b][c];
            if (p > best) best = p;
        }
        int sid = (int)(0xFFFFFFFFu - (unsigned)(best & 0xFFFFFFFFull));
        g_sid[b] = sid;
        if (write_ids) ids_out[(size_t)b * TT + t] = (float)sid;
    }
}

// ---------------- launch -----------------------------------------------------
extern "C" void kernel_launch(void* const* d_in, const int* in_sizes, int n_in,
                              void* d_out, int out_size) {
    (void)in_sizes;
    int o = (n_in >= 11) ? 1 : 0;   // optional max_length scalar at slot 1
    const int*   inputs      = (const int*)  d_in[0];
    const float* init_hidden = (const float*)d_in[1 + o];
    const float* att         = (const float*)d_in[2 + o];
    const float* emb         = (const float*)d_in[3 + o];
    const float* W_ih        = (const float*)d_in[4 + o];
    const float* W_hh        = (const float*)d_in[5 + o];
    const float* b_ih        = (const float*)d_in[6 + o];
    const float* b_hh        = (const float*)d_in[7 + o];
    const float* W_out       = (const float*)d_in[8 + o];
    const float* b_out       = (const float*)d_in[9 + o];
    float* out = (float*)d_out;

    const long long TBV = (long long)TT * BB * VV;
    const int has_ids   = ((long long)out_size >= TBV + (long long)BB * TT) ? 1 : 0;
    float* ids_out = out + TBV;

    // per-step PRNG keys: partitionable (fold-like) split of key(42)
    unsigned keys[TT][2];
    for (int t = 0; t < TT; ++t) {
        unsigned a, b;
        tf2x32(0u, 42u, 0u, (unsigned)t, &a, &b);
        keys[t][0] = a; keys[t][1] = b;
    }

    init_kernel<<<(BB * HH) / 256, 256>>>(init_hidden, att);
    for (int t = 0; t < TT; ++t) {
        gates_gemm<<<96, 256>>>(emb, inputs, W_ih, W_hh, b_ih, b_hh, t);
        hnew_kernel<<<(BB * HH) / 256, 256>>>();
        logits_hmma<<<VV / 128, 256>>>(W_out, b_out, out + (size_t)t * BB * VV);
        sample_kernel<<<dim3(SCH, BB), 256>>>(out + (size_t)t * BB * VV,
                                              keys[t][0], keys[t][1]);
        record_kernel<<<1, 64>>>(ids_out, t, has_ids);
    }
}

// round 11
// speedup vs baseline: 1.8876x; 1.0503x over previous
#include <cuda_runtime.h>
#include <cuda_fp16.h>
#include <cstdint>
#include <cstddef>

// Problem constants
#define BB    64
#define VV    32000
#define EE    512
#define HH    1024
#define G3    3072
#define TT    64
#define DINIT 768
#define DATT  256

// logits HMMA tiling
#define KCH   32           // K-chunk
#define NKC   (HH / KCH)   // 32 chunks
#define WP    40           // SMEM row pitch in fp16 (80B, conflict-free LDSM)

// ---------------- scratch (device globals; no allocations allowed) ----------
__device__ float g_h[BB * HH];                 // hidden state (in-place update)
__device__ float g_gi[BB * G3];                // x @ W_ih^T + b_ih
__device__ float g_gh[BB * G3];                // h @ W_hh^T + b_hh
__device__ int   g_sid[BB];                    // sampled ids (feedback)
__device__ unsigned long long g_slots[BB];     // packed argmax slots
__device__ __half g_w1[(size_t)VV * HH];       // W_out fp16 high part
__device__ __half g_w2[(size_t)VV * HH];       // W_out fp16 low part

// ---------------- f32x2 packed math helpers (gates gemm) --------------------
__device__ __forceinline__ unsigned long long pack2(float lo, float hi) {
    unsigned long long r;
    asm("mov.b64 %0, {%1,%2};" : "=l"(r) : "f"(lo), "f"(hi));
    return r;
}
__device__ __forceinline__ unsigned long long fma2(unsigned long long a,
                                                   unsigned long long b,
                                                   unsigned long long c) {
    unsigned long long d;
    asm("fma.rn.f32x2 %0, %1, %2, %3;" : "=l"(d) : "l"(a), "l"(b), "l"(c));
    return d;
}
__device__ __forceinline__ float2 unpack2(unsigned long long v) {
    float2 f;
    asm("mov.b64 {%0,%1}, %2;" : "=f"(f.x), "=f"(f.y) : "l"(v));
    return f;
}

// ---------------- HMMA helpers ------------------------------------------------
__device__ __forceinline__ uint32_t smem_u32(const void* p) {
    uint32_t a;
    asm("{ .reg .u64 t; cvta.to.shared.u64 t, %1; cvt.u32.u64 %0, t; }"
        : "=r"(a) : "l"(p));
    return a;
}
__device__ __forceinline__ void ldsm4(uint32_t* r, uint32_t addr) {
    asm volatile("ldmatrix.sync.aligned.m8n8.x4.shared.b16 {%0,%1,%2,%3}, [%4];"
                 : "=r"(r[0]), "=r"(r[1]), "=r"(r[2]), "=r"(r[3]) : "r"(addr));
}
__device__ __forceinline__ void mma16816(float* d, const uint32_t* a,
                                         const uint32_t* b) {
    asm volatile(
        "mma.sync.aligned.m16n8k16.row.col.f32.f16.f16.f32 "
        "{%0,%1,%2,%3}, {%4,%5,%6,%7}, {%8,%9}, {%0,%1,%2,%3};"
        : "+f"(d[0]), "+f"(d[1]), "+f"(d[2]), "+f"(d[3])
        : "r"(a[0]), "r"(a[1]), "r"(a[2]), "r"(a[3]), "r"(b[0]), "r"(b[1]));
}
__device__ __forceinline__ uint32_t pack_lohi(unsigned short lo,
                                              unsigned short hi) {
    return (uint32_t)lo | ((uint32_t)hi << 16);
}
__device__ __forceinline__ void split2(float x, unsigned short& s1,
                                       unsigned short& s2) {
    __half h1 = __float2half_rn(x);
    float f1 = __half2float(h1);
    __half h2 = __float2half_rn(x - f1);
    s1 = __half_as_ushort(h1);
    s2 = __half_as_ushort(h2);
}

// ---------------- threefry2x32 (exact JAX schedule) --------------------------
__host__ __device__ static inline void tf2x32(unsigned k0, unsigned k1,
                                              unsigned x0, unsigned x1,
                                              unsigned* o0, unsigned* o1) {
    unsigned ks2 = k0 ^ k1 ^ 0x1BD11BDAu;
#define TF_RND(R) { x0 += x1; x1 = (x1 << (R)) | (x1 >> (32 - (R))); x1 ^= x0; }
    x0 += k0; x1 += k1;
    TF_RND(13) TF_RND(15) TF_RND(26) TF_RND(6)
    x0 += k1;  x1 += ks2 + 1u;
    TF_RND(17) TF_RND(29) TF_RND(16) TF_RND(24)
    x0 += ks2; x1 += k0 + 2u;
    TF_RND(13) TF_RND(15) TF_RND(26) TF_RND(6)
    x0 += k0;  x1 += k1 + 3u;
    TF_RND(17) TF_RND(29) TF_RND(16) TF_RND(24)
    x0 += k1;  x1 += ks2 + 4u;
    TF_RND(13) TF_RND(15) TF_RND(26) TF_RND(6)
    x0 += ks2; x1 += k0 + 5u;
#undef TF_RND
    *o0 = x0; *o1 = x1;
}

__device__ __forceinline__ unsigned jax_bits32(unsigned k0, unsigned k1,
                                               unsigned e) {
    unsigned o0, o1;
    tf2x32(k0, k1, 0u, e, &o0, &o1);
    return o0 ^ o1;
}

__device__ __forceinline__ float gumbel_from_bits(unsigned bits) {
    float u = __uint_as_float((bits >> 9) | 0x3f800000u) - 1.0f;
    u = u + 1.17549435082228750797e-38f;   // == max(tiny, u0) in fp32
    return -logf(-logf(u));
}

__device__ __forceinline__ unsigned orderf(float f) {
    unsigned u = __float_as_uint(f);
    return (u & 0x80000000u) ? ~u : (u | 0x80000000u);
}

__device__ __forceinline__ unsigned long long gpack(float val, int v) {
    return ((unsigned long long)orderf(val) << 32) |
           (0xFFFFFFFFu - (unsigned)v);
}

// ---------------- W_out fp16 split precompute (runs once per launch) ---------
__global__ __launch_bounds__(256) void wsplit_kernel(const float* __restrict__ W) {
    size_t i = ((size_t)blockIdx.x * 256 + threadIdx.x) * 8;
    float4 x0 = *(const float4*)(W + i);
    float4 x1 = *(const float4*)(W + i + 4);
    const float* xs = (const float*)&x0;
    unsigned short s1[8], s2[8];
#pragma unroll
    for (int j = 0; j < 4; ++j) split2(xs[j], s1[j], s2[j]);
    const float* ys = (const float*)&x1;
#pragma unroll
    for (int j = 0; j < 4; ++j) split2(ys[j], s1[4 + j], s2[4 + j]);
    uint4 p1, p2;
    p1.x = pack_lohi(s1[0], s1[1]); p1.y = pack_lohi(s1[2], s1[3]);
    p1.z = pack_lohi(s1[4], s1[5]); p1.w = pack_lohi(s1[6], s1[7]);
    p2.x = pack_lohi(s2[0], s2[1]); p2.y = pack_lohi(s2[2], s2[3]);
    p2.z = pack_lohi(s2[4], s2[5]); p2.w = pack_lohi(s2[6], s2[7]);
    *(uint4*)(g_w1 + i) = p1;
    *(uint4*)(g_w2 + i) = p2;
}

// ---------------- init: h0 = concat(init_hidden, att_embedding) --------------
__global__ void init_kernel(const float* __restrict__ init_hidden,
                            const float* __restrict__ att) {
    int i = blockIdx.x * blockDim.x + threadIdx.x;   // [0, B*H)
    int b = i / HH, u = i % HH;
    g_h[i] = (u < DINIT) ? init_hidden[b * DINIT + u]
                         : att[b * DATT + (u - DINIT)];
}

// ---------------- gates SGEMM: 64x64 tiles (f32x2) ---------------------------
__global__ __launch_bounds__(256) void gates_gemm(
    const float* __restrict__ emb,
    const int*   __restrict__ inputs,
    const float* __restrict__ Wih, const float* __restrict__ Whh,
    const float* __restrict__ bih, const float* __restrict__ bhh,
    int t) {

    __shared__ __align__(16) float As[16][64];
    __shared__ __align__(16) float Bs[16][64];
    __shared__ const float* rowp[64];

    const float* W; const float* bias; float* C;
    int K, ncol0;
    bool gather = false;
    if (blockIdx.x < 48) {
        gather = true; W = Wih; bias = bih; C = g_gi;
        K = EE; ncol0 = blockIdx.x * 64;
    } else {
        W = Whh; bias = bhh; C = g_gh;
        K = HH; ncol0 = (blockIdx.x - 48) * 64;
    }

    const int tid = threadIdx.x;
    if (tid < 64) {
        if (gather) {
            int sid = (t == 0) ? inputs[tid] : g_sid[tid];
            rowp[tid] = emb + (size_t)sid * EE;
        } else {
            rowp[tid] = g_h + (size_t)tid * HH;
        }
    }
    __syncthreads();

    const int lm = tid >> 2;
    const int lk = (tid & 3) << 2;

    {
        float4 a  = *(const float4*)(rowp[lm] + lk);
        float4 bt = *(const float4*)(W + (size_t)(ncol0 + lm) * K + lk);
        As[lk + 0][lm] = a.x;  As[lk + 1][lm] = a.y;
        As[lk + 2][lm] = a.z;  As[lk + 3][lm] = a.w;
        Bs[lk + 0][lm] = bt.x; Bs[lk + 1][lm] = bt.y;
        Bs[lk + 2][lm] = bt.z; Bs[lk + 3][lm] = bt.w;
    }
    __syncthreads();

    const int tx = tid & 15;
    const int ty = tid >> 4;

    unsigned long long acc[2][4];
#pragma unroll
    for (int p = 0; p < 2; ++p)
#pragma unroll
        for (int n = 0; n < 4; ++n) acc[p][n] = 0ull;

    const int KT = K >> 4;
    for (int kt = 0; kt < KT; ++kt) {
        float4 an, bn;
        if (kt + 1 < KT) {
            int k0 = (kt + 1) << 4;
            an = *(const float4*)(rowp[lm] + k0 + lk);
            bn = *(const float4*)(W + (size_t)(ncol0 + lm) * K + k0 + lk);
        }
#pragma unroll
        for (int kk = 0; kk < 16; ++kk) {
            ulonglong2 av = *(const ulonglong2*)&As[kk][ty << 2];
            float4     bv = *(const float4*)&Bs[kk][tx << 2];
            unsigned long long b0 = pack2(bv.x, bv.x);
            unsigned long long b1 = pack2(bv.y, bv.y);
            unsigned long long b2 = pack2(bv.z, bv.z);
            unsigned long long b3 = pack2(bv.w, bv.w);
            acc[0][0] = fma2(av.x, b0, acc[0][0]);
            acc[0][1] = fma2(av.x, b1, acc[0][1]);
            acc[0][2] = fma2(av.x, b2, acc[0][2]);
            acc[0][3] = fma2(av.x, b3, acc[0][3]);
            acc[1][0] = fma2(av.y, b0, acc[1][0]);
            acc[1][1] = fma2(av.y, b1, acc[1][1]);
            acc[1][2] = fma2(av.y, b2, acc[1][2]);
            acc[1][3] = fma2(av.y, b3, acc[1][3]);
        }
        __syncthreads();
        if (kt + 1 < KT) {
            As[lk + 0][lm] = an.x; As[lk + 1][lm] = an.y;
            As[lk + 2][lm] = an.z; As[lk + 3][lm] = an.w;
            Bs[lk + 0][lm] = bn.x; Bs[lk + 1][lm] = bn.y;
            Bs[lk + 2][lm] = bn.z; Bs[lk + 3][lm] = bn.w;
            __syncthreads();
        }
    }

    const int m0 = ty << 2;
    const int n0 = ncol0 + (tx << 2);
    float4 bsv = *(const float4*)(bias + n0);
#pragma unroll
    for (int p = 0; p < 2; ++p) {
        float2 c0 = unpack2(acc[p][0]);
        float2 c1 = unpack2(acc[p][1]);
        float2 c2 = unpack2(acc[p][2]);
        float2 c3 = unpack2(acc[p][3]);
        int r0 = m0 + 2 * p;
        float4 w0 = make_float4(c0.x + bsv.x, c1.x + bsv.y, c2.x + bsv.z, c3.x + bsv.w);
        float4 w1 = make_float4(c0.y + bsv.x, c1.y + bsv.y, c2.y + bsv.z, c3.y + bsv.w);
        *(float4*)(C + (size_t)r0 * G3 + n0)       = w0;
        *(float4*)(C + (size_t)(r0 + 1) * G3 + n0) = w1;
    }
}

// ---------------- logits via HMMA + fused gumbel-max sampling ----------------
// C[b, v] = h[b,:] @ W_out[v,:]^T + b_out[v]
// CTA: M=64 (batch) x N=128 (vocab tile), grid = VV/128 = 250, 8 warps.
// W preconverted to fp16 (g_w1/g_w2); h split per chunk.
// Epilogue computes gumbel(b,v) for its tile and atomicMax's into g_slots.
__global__ __launch_bounds__(256) void logits_hmma(
    const float* __restrict__ bout, float* __restrict__ out,
    unsigned k0, unsigned k1) {

    __shared__ __align__(16) unsigned short sH1[64 * WP];
    __shared__ __align__(16) unsigned short sH2[64 * WP];
    __shared__ __align__(16) unsigned short sW1[128 * WP];
    __shared__ __align__(16) unsigned short sW2[128 * WP];

    const int tid = threadIdx.x;
    const int wid = tid >> 5, lid = tid & 31;
    const int v0 = blockIdx.x * 128;

    // global load mapping (per chunk of 32 k)
    const int wrow = tid >> 1, wk = (tid & 1) << 4;   // W: 128 rows x 32 k
    const int hrow = tid >> 2, hk = (tid & 3) << 3;   // h: 64 rows x 32 k
    const __half* w1p = g_w1 + (size_t)(v0 + wrow) * HH + wk;
    const __half* w2p = g_w2 + (size_t)(v0 + wrow) * HH + wk;
    const float*  hptr = g_h + (size_t)hrow * HH + hk;

    uint4 w1re[2], w2re[2];
    float4 hre[2];
    w1re[0] = *(const uint4*)(w1p);     w1re[1] = *(const uint4*)(w1p + 8);
    w2re[0] = *(const uint4*)(w2p);     w2re[1] = *(const uint4*)(w2p + 8);
#pragma unroll
    for (int j = 0; j < 2; ++j) hre[j] = *(const float4*)(hptr + 4 * j);

    const int m0 = (wid & 1) << 5;    // batch offset of warp tile
    const int n0 = (wid >> 1) << 5;   // vocab offset within CTA tile

    float acc[2][4][4];
#pragma unroll
    for (int mm = 0; mm < 2; ++mm)
#pragma unroll
        for (int nn = 0; nn < 4; ++nn)
#pragma unroll
            for (int q = 0; q < 4; ++q) acc[mm][nn][q] = 0.0f;

    const uint32_t aH1 = smem_u32(sH1), aH2 = smem_u32(sH2);
    const uint32_t aW1 = smem_u32(sW1), aW2 = smem_u32(sW2);

    const int lj = lid >> 3, lr = lid & 7;   // ldmatrix lane decomposition

    for (int c = 0; c < NKC; ++c) {
        // ---- store W chunk (already fp16) ----
        {
            uint4* d1 = (uint4*)&sW1[wrow * WP + wk];
            uint4* d2 = (uint4*)&sW2[wrow * WP + wk];
            d1[0] = w1re[0]; d1[1] = w1re[1];
            d2[0] = w2re[0]; d2[1] = w2re[1];
        }
        // ---- convert + store h chunk ----
        {
            unsigned short s1[8], s2[8];
            const float* xs = (const float*)hre;
#pragma unroll
            for (int j = 0; j < 8; ++j) split2(xs[j], s1[j], s2[j]);
            uint32_t* d1 = (uint32_t*)&sH1[hrow * WP + hk];
            uint32_t* d2 = (uint32_t*)&sH2[hrow * WP + hk];
#pragma unroll
            for (int j = 0; j < 4; ++j) {
                d1[j] = pack_lohi(s1[2 * j], s1[2 * j + 1]);
                d2[j] = pack_lohi(s2[2 * j], s2[2 * j + 1]);
            }
        }
        __syncthreads();

        // prefetch next chunk (overlaps with MMA)
        if (c + 1 < NKC) {
            const int koff = (c + 1) * KCH;
            w1re[0] = *(const uint4*)(w1p + koff);
            w1re[1] = *(const uint4*)(w1p + koff + 8);
            w2re[0] = *(const uint4*)(w2p + koff);
            w2re[1] = *(const uint4*)(w2p + koff + 8);
            const float* hn = hptr + koff;
#pragma unroll
            for (int j = 0; j < 2; ++j) hre[j] = *(const float4*)(hn + 4 * j);
        }

#pragma unroll
        for (int ks = 0; ks < 2; ++ks) {
            const int kb = ks << 4;

            // A fragments (h): 2 m16k16 frags per level
            uint32_t a1[2][4], a2[2][4];
#pragma unroll
            for (int mm = 0; mm < 2; ++mm) {
                int row = m0 + (mm << 4) + ((lj & 1) << 3) + lr;
                int col = kb + ((lj >> 1) << 3);
                uint32_t off = (uint32_t)(row * WP + col) * 2;
                ldsm4(a1[mm], aH1 + off);
                ldsm4(a2[mm], aH2 + off);
            }
            // B fragments (W): 4 n8k16 frags per level (2 LDSM.x4 each)
            uint32_t b1[4][2], b2[4][2];
#pragma unroll
            for (int p = 0; p < 2; ++p) {
                int row = n0 + (p << 4) + ((lj >> 1) << 3) + lr;
                int col = kb + ((lj & 1) << 3);
                uint32_t off = (uint32_t)(row * WP + col) * 2;
                uint32_t t[4];
                ldsm4(t, aW1 + off);
                b1[2 * p][0] = t[0]; b1[2 * p][1] = t[1];
                b1[2 * p + 1][0] = t[2]; b1[2 * p + 1][1] = t[3];
                ldsm4(t, aW2 + off);
                b2[2 * p][0] = t[0]; b2[2 * p][1] = t[1];
                b2[2 * p + 1][0] = t[2]; b2[2 * p + 1][1] = t[3];
            }

            // 3 split terms: h1w1 + h2w1 + h1w2
#pragma unroll
            for (int mm = 0; mm < 2; ++mm)
#pragma unroll
                for (int nn = 0; nn < 4; ++nn) {
                    mma16816(acc[mm][nn], a1[mm], b1[nn]);
                    mma16816(acc[mm][nn], a2[mm], b1[nn]);
                    mma16816(acc[mm][nn], a1[mm], b2[nn]);
                }
        }
        __syncthreads();
    }

    // ---- epilogue: add bias, write logits, fused gumbel partial argmax ----
    unsigned long long bst[2][2] = {{0ull, 0ull}, {0ull, 0ull}};
#pragma unroll
    for (int nn = 0; nn < 4; ++nn) {
        int v = v0 + n0 + (nn << 3) + ((lid & 3) << 1);
        float2 bias = *(const float2*)(bout + v);
#pragma unroll
        for (int mm = 0; mm < 2; ++mm) {
            int b0i = m0 + (mm << 4) + (lid >> 2);
            float v00 = acc[mm][nn][0] + bias.x;
            float v01 = acc[mm][nn][1] + bias.y;
            float v10 = acc[mm][nn][2] + bias.x;
            float v11 = acc[mm][nn][3] + bias.y;
            *(float2*)(out + (size_t)b0i * VV + v)       = make_float2(v00, v01);
            *(float2*)(out + (size_t)(b0i + 8) * VV + v) = make_float2(v10, v11);

            unsigned e0 = (unsigned)(b0i * VV + v);
            unsigned e1 = (unsigned)((b0i + 8) * VV + v);
            unsigned long long p;
            p = gpack(v00 + gumbel_from_bits(jax_bits32(k0, k1, e0)), v);
            if (p > bst[mm][0]) bst[mm][0] = p;
            p = gpack(v01 + gumbel_from_bits(jax_bits32(k0, k1, e0 + 1)), v + 1);
            if (p > bst[mm][0]) bst[mm][0] = p;
            p = gpack(v10 + gumbel_from_bits(jax_bits32(k0, k1, e1)), v);
            if (p > bst[mm][1]) bst[mm][1] = p;
            p = gpack(v11 + gumbel_from_bits(jax_bits32(k0, k1, e1 + 1)), v + 1);
            if (p > bst[mm][1]) bst[mm][1] = p;
        }
    }
    // reduce across the 4 lanes sharing each batch row, then atomicMax
#pragma unroll
    for (int mm = 0; mm < 2; ++mm)
#pragma unroll
        for (int r = 0; r < 2; ++r) {
            unsigned long long x = bst[mm][r];
            unsigned long long y = __shfl_xor_sync(0xFFFFFFFFu, x, 1);
            if (y > x) x = y;
            y = __shfl_xor_sync(0xFFFFFFFFu, x, 2);
            if (y > x) x = y;
            if ((lid & 3) == 0) {
                int row = m0 + (mm << 4) + (lid >> 2) + 8 * r;
                atomicMax(&g_slots[row], x);
            }
        }
}

// ---------------- GRU elementwise update + slot reset ------------------------
__global__ void hnew_kernel() {
    int i = blockIdx.x * blockDim.x + threadIdx.x;   // [0, B*H)
    int b = i / HH, u = i % HH;
    const float* gi = g_gi + (size_t)b * G3;
    const float* gh = g_gh + (size_t)b * G3;
    float ir = gi[u], iz = gi[HH + u], in_ = gi[2 * HH + u];
    float hr = gh[u], hz = gh[HH + u], hn  = gh[2 * HH + u];
    float r = 1.0f / (1.0f + expf(-(ir + hr)));
    float z = 1.0f / (1.0f + expf(-(iz + hz)));
    float n = tanhf(in_ + r * hn);
    float h = g_h[i];
    g_h[i] = (1.0f - z) * n + z * h;
    if (i < BB) g_slots[i] = 0ull;   // reset argmax slots before logits+sample
}

// ---------------- final reduce: slots -> g_sid + ids_out ---------------------
__global__ void record_kernel(float* __restrict__ ids_out, int t, int write_ids) {
    int b = threadIdx.x;
    if (b < BB) {
        int sid = (int)(0xFFFFFFFFu - (unsigned)(g_slots[b] & 0xFFFFFFFFull));
        g_sid[b] = sid;
        if (write_ids) ids_out[(size_t)b * TT + t] = (float)sid;
    }
}

// ---------------- launch -----------------------------------------------------
extern "C" void kernel_launch(void* const* d_in, const int* in_sizes, int n_in,
                              void* d_out, int out_size) {
    (void)in_sizes;
    int o = (n_in >= 11) ? 1 : 0;   // optional max_length scalar at slot 1
    const int*   inputs      = (const int*)  d_in[0];
    const float* init_hidden = (const float*)d_in[1 + o];
    const float* att         = (const float*)d_in[2 + o];
    const float* emb         = (const float*)d_in[3 + o];
    const float* W_ih        = (const float*)d_in[4 + o];
    const float* W_hh        = (const float*)d_in[5 + o];
    const float* b_ih        = (const float*)d_in[6 + o];
    const float* b_hh        = (const float*)d_in[7 + o];
    const float* W_out       = (const float*)d_in[8 + o];
    const float* b_out       = (const float*)d_in[9 + o];
    float* out = (float*)d_out;

    const long long TBV = (long long)TT * BB * VV;
    const int has_ids   = ((long long)out_size >= TBV + (long long)BB * TT) ? 1 : 0;
    float* ids_out = out + TBV;

    // per-step PRNG keys: partitionable (fold-like) split of key(42)
    unsigned keys[TT][2];
    for (int t = 0; t < TT; ++t) {
        unsigned a, b;
        tf2x32(0u, 42u, 0u, (unsigned)t, &a, &b);
        keys[t][0] = a; keys[t][1] = b;
    }

    // one-time (per launch) W_out fp16 split:  VV*HH / (256*8) blocks
    wsplit_kernel<<<(VV * HH) / (256 * 8), 256>>>(W_out);
    init_kernel<<<(BB * HH) / 256, 256>>>(init_hidden, att);
    for (int t = 0; t < TT; ++t) {
        gates_gemm<<<96, 256>>>(emb, inputs, W_ih, W_hh, b_ih, b_hh, t);
        hnew_kernel<<<(BB * HH) / 256, 256>>>();
        logits_hmma<<<VV / 128, 256>>>(b_out, out + (size_t)t * BB * VV,
                                       keys[t][0], keys[t][1]);
        record_kernel<<<1, 64>>>(ids_out, t, has_ids);
    }
}

// round 14
// speedup vs baseline: 1.9482x; 1.0321x over previous
#include <cuda_runtime.h>
#include <cuda_fp16.h>
#include <cstdint>
#include <cstddef>

// Problem constants
#define BB    64
#define VV    32000
#define EE    512
#define HH    1024
#define G3    3072
#define TT    64
#define DINIT 768
#define DATT  256

// logits HMMA tiling
#define KCH   32           // K-chunk
#define NKC   (HH / KCH)   // 32 chunks
#define NKS   (HH / 16)    // 64 k16-steps
#define NG    (VV / 8)     // 4000 n8-groups
#define WP    40           // SMEM row pitch in fp16 (80B, conflict-free LDSM)

// ---------------- scratch (device globals; no allocations allowed) ----------
__device__ float g_h[BB * HH];                 // hidden state (in-place update)
__device__ float g_gi[BB * G3];                // x @ W_ih^T + b_ih
__device__ float g_gh[BB * G3];                // h @ W_hh^T + b_hh
__device__ int   g_sid[BB];                    // sampled ids (feedback)
__device__ unsigned long long g_slots[BB];     // packed argmax slots
// W_out fp16 2-level split, MMA B-fragment order:
// uint4 {w1b0, w1b1, w2b0, w2b1} at [(g * NKS + ks) * 32 + lane]
__device__ uint4 g_wf[(size_t)NG * NKS * 32];

// ---------------- f32x2 packed math helpers (gates gemm) --------------------
__device__ __forceinline__ unsigned long long pack2(float lo, float hi) {
    unsigned long long r;
    asm("mov.b64 %0, {%1,%2};" : "=l"(r) : "f"(lo), "f"(hi));
    return r;
}
__device__ __forceinline__ unsigned long long fma2(unsigned long long a,
                                                   unsigned long long b,
                                                   unsigned long long c) {
    unsigned long long d;
    asm("fma.rn.f32x2 %0, %1, %2, %3;" : "=l"(d) : "l"(a), "l"(b), "l"(c));
    return d;
}
__device__ __forceinline__ float2 unpack2(unsigned long long v) {
    float2 f;
    asm("mov.b64 {%0,%1}, %2;" : "=f"(f.x), "=f"(f.y) : "l"(v));
    return f;
}

// ---------------- HMMA helpers ------------------------------------------------
__device__ __forceinline__ uint32_t smem_u32(const void* p) {
    uint32_t a;
    asm("{ .reg .u64 t; cvta.to.shared.u64 t, %1; cvt.u32.u64 %0, t; }"
        : "=r"(a) : "l"(p));
    return a;
}
__device__ __forceinline__ void ldsm4(uint32_t* r, uint32_t addr) {
    asm volatile("ldmatrix.sync.aligned.m8n8.x4.shared.b16 {%0,%1,%2,%3}, [%4];"
                 : "=r"(r[0]), "=r"(r[1]), "=r"(r[2]), "=r"(r[3]) : "r"(addr));
}
__device__ __forceinline__ void mma16816(float* d, const uint32_t* a,
                                         uint32_t b0, uint32_t b1) {
    asm volatile(
        "mma.sync.aligned.m16n8k16.row.col.f32.f16.f16.f32 "
        "{%0,%1,%2,%3}, {%4,%5,%6,%7}, {%8,%9}, {%0,%1,%2,%3};"
        : "+f"(d[0]), "+f"(d[1]), "+f"(d[2]), "+f"(d[3])
        : "r"(a[0]), "r"(a[1]), "r"(a[2]), "r"(a[3]), "r"(b0), "r"(b1));
}
__device__ __forceinline__ uint32_t pack_lohi(unsigned short lo,
                                              unsigned short hi) {
    return (uint32_t)lo | ((uint32_t)hi << 16);
}
__device__ __forceinline__ void split2(float x, unsigned short& s1,
                                       unsigned short& s2) {
    __half h1 = __float2half_rn(x);
    float f1 = __half2float(h1);
    __half h2 = __float2half_rn(x - f1);
    s1 = __half_as_ushort(h1);
    s2 = __half_as_ushort(h2);
}

// ---------------- threefry2x32 (exact JAX schedule) --------------------------
__host__ __device__ static inline void tf2x32(unsigned k0, unsigned k1,
                                              unsigned x0, unsigned x1,
                                              unsigned* o0, unsigned* o1) {
    unsigned ks2 = k0 ^ k1 ^ 0x1BD11BDAu;
#define TF_RND(R) { x0 += x1; x1 = (x1 << (R)) | (x1 >> (32 - (R))); x1 ^= x0; }
    x0 += k0; x1 += k1;
    TF_RND(13) TF_RND(15) TF_RND(26) TF_RND(6)
    x0 += k1;  x1 += ks2 + 1u;
    TF_RND(17) TF_RND(29) TF_RND(16) TF_RND(24)
    x0 += ks2; x1 += k0 + 2u;
    TF_RND(13) TF_RND(15) TF_RND(26) TF_RND(6)
    x0 += k0;  x1 += k1 + 3u;
    TF_RND(17) TF_RND(29) TF_RND(16) TF_RND(24)
    x0 += k1;  x1 += ks2 + 4u;
    TF_RND(13) TF_RND(15) TF_RND(26) TF_RND(6)
    x0 += ks2; x1 += k0 + 5u;
#undef TF_RND
    *o0 = x0; *o1 = x1;
}

__device__ __forceinline__ unsigned jax_bits32(unsigned k0, unsigned k1,
                                               unsigned e) {
    unsigned o0, o1;
    tf2x32(k0, k1, 0u, e, &o0, &o1);
    return o0 ^ o1;
}

__device__ __forceinline__ float gumbel_from_bits(unsigned bits) {
    float u = __uint_as_float((bits >> 9) | 0x3f800000u) - 1.0f;
    u = u + 1.17549435082228750797e-38f;   // == max(tiny, u0) in fp32
    return -logf(-logf(u));
}

__device__ __forceinline__ unsigned orderf(float f) {
    unsigned u = __float_as_uint(f);
    return (u & 0x80000000u) ? ~u : (u | 0x80000000u);
}

__device__ __forceinline__ unsigned long long gpack(float val, int v) {
    return ((unsigned long long)orderf(val) << 32) |
           (0xFFFFFFFFu - (unsigned)v);
}

// ---------------- W_out fragment-order split precompute ----------------------
// thread i -> (g = i>>11, ks = (i>>5)&63, l = i&31)
// n = 8g + (l>>2), k = 16ks + 2(l&3)
// uint4 = { pack(w1[n][k],w1[n][k+1]), pack(w1[n][k+8],w1[n][k+9]),
//           pack(w2[n][k],w2[n][k+1]), pack(w2[n][k+8],w2[n][k+9]) }
__global__ __launch_bounds__(256) void wfrag_kernel(const float* __restrict__ W) {
    size_t i = (size_t)blockIdx.x * 256 + threadIdx.x;
    int l  = (int)(i & 31);
    int ks = (int)((i >> 5) & (NKS - 1));
    int g  = (int)(i >> 11);
    int n = 8 * g + (l >> 2);
    int k = 16 * ks + 2 * (l & 3);
    const float* row = W + (size_t)n * HH + k;
    float2 x0 = *(const float2*)(row);
    float2 x1 = *(const float2*)(row + 8);
    unsigned short a1, a2, b1, b2, c1, c2, d1, d2;
    split2(x0.x, a1, a2); split2(x0.y, b1, b2);
    split2(x1.x, c1, c2); split2(x1.y, d1, d2);
    uint4 p;
    p.x = pack_lohi(a1, b1);   // w1 b0
    p.y = pack_lohi(c1, d1);   // w1 b1
    p.z = pack_lohi(a2, b2);   // w2 b0
    p.w = pack_lohi(c2, d2);   // w2 b1
    g_wf[i] = p;
}

// ---------------- init: h0 = concat(init_hidden, att_embedding) --------------
__global__ void init_kernel(const float* __restrict__ init_hidden,
                            const float* __restrict__ att) {
    int i = blockIdx.x * blockDim.x + threadIdx.x;   // [0, B*H)
    int b = i / HH, u = i % HH;
    g_h[i] = (u < DINIT) ? init_hidden[b * DINIT + u]
                         : att[b * DATT + (u - DINIT)];
}

// ---------------- gates SGEMM: 64x64 tiles (f32x2) ---------------------------
__global__ __launch_bounds__(256) void gates_gemm(
    const float* __restrict__ emb,
    const int*   __restrict__ inputs,
    const float* __restrict__ Wih, const float* __restrict__ Whh,
    const float* __restrict__ bih, const float* __restrict__ bhh,
    int t) {

    __shared__ __align__(16) float As[16][64];
    __shared__ __align__(16) float Bs[16][64];
    __shared__ const float* rowp[64];

    const float* W; const float* bias; float* C;
    int K, ncol0;
    bool gather = false;
    if (blockIdx.x < 48) {
        gather = true; W = Wih; bias = bih; C = g_gi;
        K = EE; ncol0 = blockIdx.x * 64;
    } else {
        W = Whh; bias = bhh; C = g_gh;
        K = HH; ncol0 = (blockIdx.x - 48) * 64;
    }

    const int tid = threadIdx.x;
    if (tid < 64) {
        if (gather) {
            int sid = (t == 0) ? inputs[tid] : g_sid[tid];
            rowp[tid] = emb + (size_t)sid * EE;
        } else {
            rowp[tid] = g_h + (size_t)tid * HH;
        }
    }
    __syncthreads();

    const int lm = tid >> 2;
    const int lk = (tid & 3) << 2;

    {
        float4 a  = *(const float4*)(rowp[lm] + lk);
        float4 bt = *(const float4*)(W + (size_t)(ncol0 + lm) * K + lk);
        As[lk + 0][lm] = a.x;  As[lk + 1][lm] = a.y;
        As[lk + 2][lm] = a.z;  As[lk + 3][lm] = a.w;
        Bs[lk + 0][lm] = bt.x; Bs[lk + 1][lm] = bt.y;
        Bs[lk + 2][lm] = bt.z; Bs[lk + 3][lm] = bt.w;
    }
    __syncthreads();

    const int tx = tid & 15;
    const int ty = tid >> 4;

    unsigned long long acc[2][4];
#pragma unroll
    for (int p = 0; p < 2; ++p)
#pragma unroll
        for (int n = 0; n < 4; ++n) acc[p][n] = 0ull;

    const int KT = K >> 4;
    for (int kt = 0; kt < KT; ++kt) {
        float4 an, bn;
        if (kt + 1 < KT) {
            int k0 = (kt + 1) << 4;
            an = *(const float4*)(rowp[lm] + k0 + lk);
            bn = *(const float4*)(W + (size_t)(ncol0 + lm) * K + k0 + lk);
        }
#pragma unroll
        for (int kk = 0; kk < 16; ++kk) {
            ulonglong2 av = *(const ulonglong2*)&As[kk][ty << 2];
            float4     bv = *(const float4*)&Bs[kk][tx << 2];
            unsigned long long b0 = pack2(bv.x, bv.x);
            unsigned long long b1 = pack2(bv.y, bv.y);
            unsigned long long b2 = pack2(bv.z, bv.z);
            unsigned long long b3 = pack2(bv.w, bv.w);
            acc[0][0] = fma2(av.x, b0, acc[0][0]);
            acc[0][1] = fma2(av.x, b1, acc[0][1]);
            acc[0][2] = fma2(av.x, b2, acc[0][2]);
            acc[0][3] = fma2(av.x, b3, acc[0][3]);
            acc[1][0] = fma2(av.y, b0, acc[1][0]);
            acc[1][1] = fma2(av.y, b1, acc[1][1]);
            acc[1][2] = fma2(av.y, b2, acc[1][2]);
            acc[1][3] = fma2(av.y, b3, acc[1][3]);
        }
        __syncthreads();
        if (kt + 1 < KT) {
            As[lk + 0][lm] = an.x; As[lk + 1][lm] = an.y;
            As[lk + 2][lm] = an.z; As[lk + 3][lm] = an.w;
            Bs[lk + 0][lm] = bn.x; Bs[lk + 1][lm] = bn.y;
            Bs[lk + 2][lm] = bn.z; Bs[lk + 3][lm] = bn.w;
            __syncthreads();
        }
    }

    const int m0 = ty << 2;
    const int n0 = ncol0 + (tx << 2);
    float4 bsv = *(const float4*)(bias + n0);
#pragma unroll
    for (int p = 0; p < 2; ++p) {
        float2 c0 = unpack2(acc[p][0]);
        float2 c1 = unpack2(acc[p][1]);
        float2 c2 = unpack2(acc[p][2]);
        float2 c3 = unpack2(acc[p][3]);
        int r0 = m0 + 2 * p;
        float4 w0 = make_float4(c0.x + bsv.x, c1.x + bsv.y, c2.x + bsv.z, c3.x + bsv.w);
        float4 w1 = make_float4(c0.y + bsv.x, c1.y + bsv.y, c2.y + bsv.z, c3.y + bsv.w);
        *(float4*)(C + (size_t)r0 * G3 + n0)       = w0;
        *(float4*)(C + (size_t)(r0 + 1) * G3 + n0) = w1;
    }
}

// ---------------- logits via HMMA + fused gumbel-max sampling ----------------
// C[b, v] = h[b,:] @ W_out[v,:]^T + b_out[v]
// CTA: M=64 (batch) x N=128 (vocab tile), grid = 250, 8 warps.
// A (h): split per chunk into SMEM, LDSM.  B (W): fragment-direct LDG from g_wf.
__global__ __launch_bounds__(256) void logits_hmma(
    const float* __restrict__ bout, float* __restrict__ out,
    unsigned k0, unsigned k1) {

    __shared__ __align__(16) unsigned short sH1[64 * WP];
    __shared__ __align__(16) unsigned short sH2[64 * WP];

    const int tid = threadIdx.x;
    const int wid = tid >> 5, lid = tid & 31;
    const int v0 = blockIdx.x * 128;

    // h global load mapping (per chunk of 32 k)
    const int hrow = tid >> 2, hk = (tid & 3) << 3;   // h: 64 rows x 32 k
    const float* hptr = g_h + (size_t)hrow * HH + hk;

    float4 hre[2];
#pragma unroll
    for (int j = 0; j < 2; ++j) hre[j] = *(const float4*)(hptr + 4 * j);

    const int m0 = (wid & 1) << 5;    // batch offset of warp tile
    const int n0 = (wid >> 1) << 5;   // vocab offset within CTA tile

    // B fragment stream base: 4 n8-groups per warp
    const int gw = blockIdx.x * 16 + (n0 >> 3);
    const uint4* wfp = g_wf + ((size_t)gw * NKS) * 32 + lid;

    float acc[2][4][4];
#pragma unroll
    for (int mm = 0; mm < 2; ++mm)
#pragma unroll
        for (int nn = 0; nn < 4; ++nn)
#pragma unroll
            for (int q = 0; q < 4; ++q) acc[mm][nn][q] = 0.0f;

    const uint32_t aH1 = smem_u32(sH1), aH2 = smem_u32(sH2);
    const int lj = lid >> 3, lr = lid & 7;   // ldmatrix lane decomposition

    // preload B fragments for ks=0
    uint4 bcur[4], bnxt[4];
#pragma unroll
    for (int nn = 0; nn < 4; ++nn) bcur[nn] = wfp[(size_t)nn * NKS * 32];

    for (int c = 0; c < NKC; ++c) {
        // ---- convert + store h chunk ----
        {
            unsigned short s1[8], s2[8];
            const float* xs = (const float*)hre;
#pragma unroll
            for (int j = 0; j < 8; ++j) split2(xs[j], s1[j], s2[j]);
            uint32_t* d1 = (uint32_t*)&sH1[hrow * WP + hk];
            uint32_t* d2 = (uint32_t*)&sH2[hrow * WP + hk];
#pragma unroll
            for (int j = 0; j < 4; ++j) {
                d1[j] = pack_lohi(s1[2 * j], s1[2 * j + 1]);
                d2[j] = pack_lohi(s2[2 * j], s2[2 * j + 1]);
            }
        }
        __syncthreads();

        // prefetch next h chunk
        if (c + 1 < NKC) {
            const float* hn = hptr + (c + 1) * KCH;
#pragma unroll
            for (int j = 0; j < 2; ++j) hre[j] = *(const float4*)(hn + 4 * j);
        }

#pragma unroll
        for (int ks = 0; ks < 2; ++ks) {
            const int kb = ks << 4;
            const int ksi = c * 2 + ks;

            // prefetch next ks B fragments (crosses chunk boundary freely)
            if (ksi + 1 < NKS) {
#pragma unroll
                for (int nn = 0; nn < 4; ++nn)
                    bnxt[nn] = wfp[((size_t)nn * NKS + (ksi + 1)) * 32];
            }

            // A fragments (h): 2 m16k16 frags per level
            uint32_t a1[2][4], a2[2][4];
#pragma unroll
            for (int mm = 0; mm < 2; ++mm) {
                int row = m0 + (mm << 4) + ((lj & 1) << 3) + lr;
                int col = kb + ((lj >> 1) << 3);
                uint32_t off = (uint32_t)(row * WP + col) * 2;
                ldsm4(a1[mm], aH1 + off);
                ldsm4(a2[mm], aH2 + off);
            }

            // 3 split terms: h1w1 + h2w1 + h1w2
#pragma unroll
            for (int mm = 0; mm < 2; ++mm)
#pragma unroll
                for (int nn = 0; nn < 4; ++nn) {
                    mma16816(acc[mm][nn], a1[mm], bcur[nn].x, bcur[nn].y);
                    mma16816(acc[mm][nn], a2[mm], bcur[nn].x, bcur[nn].y);
                    mma16816(acc[mm][nn], a1[mm], bcur[nn].z, bcur[nn].w);
                }
#pragma unroll
            for (int nn = 0; nn < 4; ++nn) bcur[nn] = bnxt[nn];
        }
        __syncthreads();
    }

    // ---- epilogue: add bias, write logits, fused gumbel partial argmax ----
    unsigned long long bst[2][2] = {{0ull, 0ull}, {0ull, 0ull}};
#pragma unroll
    for (int nn = 0; nn < 4; ++nn) {
        int v = v0 + n0 + (nn << 3) + ((lid & 3) << 1);
        float2 bias = *(const float2*)(bout + v);
#pragma unroll
        for (int mm = 0; mm < 2; ++mm) {
            int b0i = m0 + (mm << 4) + (lid >> 2);
            float v00 = acc[mm][nn][0] + bias.x;
            float v01 = acc[mm][nn][1] + bias.y;
            float v10 = acc[mm][nn][2] + bias.x;
            float v11 = acc[mm][nn][3] + bias.y;
            *(float2*)(out + (size_t)b0i * VV + v)       = make_float2(v00, v01);
            *(float2*)(out + (size_t)(b0i + 8) * VV + v) = make_float2(v10, v11);

            unsigned e0 = (unsigned)(b0i * VV + v);
            unsigned e1 = (unsigned)((b0i + 8) * VV + v);
            unsigned long long p;
            p = gpack(v00 + gumbel_from_bits(jax_bits32(k0, k1, e0)), v);
            if (p > bst[mm][0]) bst[mm][0] = p;
            p = gpack(v01 + gumbel_from_bits(jax_bits32(k0, k1, e0 + 1)), v + 1);
            if (p > bst[mm][0]) bst[mm][0] = p;
            p = gpack(v10 + gumbel_from_bits(jax_bits32(k0, k1, e1)), v);
            if (p > bst[mm][1]) bst[mm][1] = p;
            p = gpack(v11 + gumbel_from_bits(jax_bits32(k0, k1, e1 + 1)), v + 1);
            if (p > bst[mm][1]) bst[mm][1] = p;
        }
    }
    // reduce across the 4 lanes sharing each batch row, then atomicMax
#pragma unroll
    for (int mm = 0; mm < 2; ++mm)
#pragma unroll
        for (int r = 0; r < 2; ++r) {
            unsigned long long x = bst[mm][r];
            unsigned long long y = __shfl_xor_sync(0xFFFFFFFFu, x, 1);
            if (y > x) x = y;
            y = __shfl_xor_sync(0xFFFFFFFFu, x, 2);
            if (y > x) x = y;
            if ((lid & 3) == 0) {
                int row = m0 + (mm << 4) + (lid >> 2) + 8 * r;
                atomicMax(&g_slots[row], x);
            }
        }
}

// ---------------- GRU elementwise update + slot reset ------------------------
__global__ void hnew_kernel() {
    int i = blockIdx.x * blockDim.x + threadIdx.x;   // [0, B*H)
    int b = i / HH, u = i % HH;
    const float* gi = g_gi + (size_t)b * G3;
    const float* gh = g_gh + (size_t)b * G3;
    float ir = gi[u], iz = gi[HH + u], in_ = gi[2 * HH + u];
    float hr = gh[u], hz = gh[HH + u], hn  = gh[2 * HH + u];
    float r = 1.0f / (1.0f + expf(-(ir + hr)));
    float z = 1.0f / (1.0f + expf(-(iz + hz)));
    float n = tanhf(in_ + r * hn);
    float h = g_h[i];
    g_h[i] = (1.0f - z) * n + z * h;
    if (i < BB) g_slots[i] = 0ull;   // reset argmax slots before logits+sample
}

// ---------------- final reduce: slots -> g_sid + ids_out ---------------------
__global__ void record_kernel(float* __restrict__ ids_out, int t, int write_ids) {
    int b = threadIdx.x;
    if (b < BB) {
        int sid = (int)(0xFFFFFFFFu - (unsigned)(g_slots[b] & 0xFFFFFFFFull));
        g_sid[b] = sid;
        if (write_ids) ids_out[(size_t)b * TT + t] = (float)sid;
    }
}

// ---------------- launch -----------------------------------------------------
extern "C" void kernel_launch(void* const* d_in, const int* in_sizes, int n_in,
                              void* d_out, int out_size) {
    (void)in_sizes;
    int o = (n_in >= 11) ? 1 : 0;   // optional max_length scalar at slot 1
    const int*   inputs      = (const int*)  d_in[0];
    const float* init_hidden = (const float*)d_in[1 + o];
    const float* att         = (const float*)d_in[2 + o];
    const float* emb         = (const float*)d_in[3 + o];
    const float* W_ih        = (const float*)d_in[4 + o];
    const float* W_hh        = (const float*)d_in[5 + o];
    const float* b_ih        = (const float*)d_in[6 + o];
    const float* b_hh        = (const float*)d_in[7 + o];
    const float* W_out       = (const float*)d_in[8 + o];
    const float* b_out       = (const float*)d_in[9 + o];
    float* out = (float*)d_out;

    const long long TBV = (long long)TT * BB * VV;
    const int has_ids   = ((long long)out_size >= TBV + (long long)BB * TT) ? 1 : 0;
    float* ids_out = out + TBV;

    // per-step PRNG keys: partitionable (fold-like) split of key(42)
    unsigned keys[TT][2];
    for (int t = 0; t < TT; ++t) {
        unsigned a, b;
        tf2x32(0u, 42u, 0u, (unsigned)t, &a, &b);
        keys[t][0] = a; keys[t][1] = b;
    }

    // one-time (per launch) W_out fragment split: NG*NKS*32 threads
    wfrag_kernel<<<(NG * NKS * 32) / 256, 256>>>(W_out);
    init_kernel<<<(BB * HH) / 256, 256>>>(init_hidden, att);
    for (int t = 0; t < TT; ++t) {
        gates_gemm<<<96, 256>>>(emb, inputs, W_ih, W_hh, b_ih, b_hh, t);
        hnew_kernel<<<(BB * HH) / 256, 256>>>();
        logits_hmma<<<VV / 128, 256>>>(b_out, out + (size_t)t * BB * VV,
                                       keys[t][0], keys[t][1]);
        record_kernel<<<1, 64>>>(ids_out, t, has_ids);
    }
}

// round 16
// speedup vs baseline: 1.9755x; 1.0141x over previous
#include <cuda_runtime.h>
#include <cuda_fp16.h>
#include <cstdint>
#include <cstddef>

// Problem constants
#define BB    64
#define VV    32000
#define EE    512
#define HH    1024
#define G3    3072
#define TT    64
#define DINIT 768
#define DATT  256

// HMMA tiling
#define KCH   32           // K-chunk
#define NKC   (HH / KCH)   // 32 chunks (logits / gh)
#define NKS   (HH / 16)    // 64 k16-steps (logits / gh)
#define NG    (VV / 8)     // 4000 n8-groups (logits)
#define NGG   (G3 / 8)     // 384 n8-groups (gates)
#define WP    40           // SMEM row pitch in fp16 (80B, conflict-free LDSM)

// ---------------- scratch (device globals; no allocations allowed) ----------
__device__ float g_h[BB * HH];                 // hidden state (in-place update)
__device__ float g_gi[BB * G3];                // x @ W_ih^T + b_ih
__device__ float g_gh[BB * G3];                // h @ W_hh^T + b_hh
__device__ unsigned long long g_slots[BB];     // packed argmax slots
// fp16 2-level split weights, MMA B-fragment order:
// uint4 {w1b0, w1b1, w2b0, w2b1} at [(g * nks + ks) * 32 + lane]
__device__ uint4 g_wf[(size_t)NG * NKS * 32];          // W_out
__device__ uint4 g_wfih[(size_t)NGG * (EE / 16) * 32]; // W_ih (nks=32)
__device__ uint4 g_wfhh[(size_t)NGG * (HH / 16) * 32]; // W_hh (nks=64)

// ---------------- HMMA helpers ------------------------------------------------
__device__ __forceinline__ uint32_t smem_u32(const void* p) {
    uint32_t a;
    asm("{ .reg .u64 t; cvta.to.shared.u64 t, %1; cvt.u32.u64 %0, t; }"
        : "=r"(a) : "l"(p));
    return a;
}
__device__ __forceinline__ void ldsm4(uint32_t* r, uint32_t addr) {
    asm volatile("ldmatrix.sync.aligned.m8n8.x4.shared.b16 {%0,%1,%2,%3}, [%4];"
                 : "=r"(r[0]), "=r"(r[1]), "=r"(r[2]), "=r"(r[3]) : "r"(addr));
}
__device__ __forceinline__ void mma16816(float* d, const uint32_t* a,
                                         uint32_t b0, uint32_t b1) {
    asm volatile(
        "mma.sync.aligned.m16n8k16.row.col.f32.f16.f16.f32 "
        "{%0,%1,%2,%3}, {%4,%5,%6,%7}, {%8,%9}, {%0,%1,%2,%3};"
        : "+f"(d[0]), "+f"(d[1]), "+f"(d[2]), "+f"(d[3])
        : "r"(a[0]), "r"(a[1]), "r"(a[2]), "r"(a[3]), "r"(b0), "r"(b1));
}
__device__ __forceinline__ uint32_t pack_lohi(unsigned short lo,
                                              unsigned short hi) {
    return (uint32_t)lo | ((uint32_t)hi << 16);
}
__device__ __forceinline__ void split2(float x, unsigned short& s1,
                                       unsigned short& s2) {
    __half h1 = __float2half_rn(x);
    float f1 = __half2float(h1);
    __half h2 = __float2half_rn(x - f1);
    s1 = __half_as_ushort(h1);
    s2 = __half_as_ushort(h2);
}

// ---------------- threefry2x32 (exact JAX schedule) --------------------------
__host__ __device__ static inline void tf2x32(unsigned k0, unsigned k1,
                                              unsigned x0, unsigned x1,
                                              unsigned* o0, unsigned* o1) {
    unsigned ks2 = k0 ^ k1 ^ 0x1BD11BDAu;
#define TF_RND(R) { x0 += x1; x1 = (x1 << (R)) | (x1 >> (32 - (R))); x1 ^= x0; }
    x0 += k0; x1 += k1;
    TF_RND(13) TF_RND(15) TF_RND(26) TF_RND(6)
    x0 += k1;  x1 += ks2 + 1u;
    TF_RND(17) TF_RND(29) TF_RND(16) TF_RND(24)
    x0 += ks2; x1 += k0 + 2u;
    TF_RND(13) TF_RND(15) TF_RND(26) TF_RND(6)
    x0 += k0;  x1 += k1 + 3u;
    TF_RND(17) TF_RND(29) TF_RND(16) TF_RND(24)
    x0 += k1;  x1 += ks2 + 4u;
    TF_RND(13) TF_RND(15) TF_RND(26) TF_RND(6)
    x0 += ks2; x1 += k0 + 5u;
#undef TF_RND
    *o0 = x0; *o1 = x1;
}

__device__ __forceinline__ unsigned jax_bits32(unsigned k0, unsigned k1,
                                               unsigned e) {
    unsigned o0, o1;
    tf2x32(k0, k1, 0u, e, &o0, &o1);
    return o0 ^ o1;
}

__device__ __forceinline__ float gumbel_from_bits(unsigned bits) {
    float u = __uint_as_float((bits >> 9) | 0x3f800000u) - 1.0f;
    u = u + 1.17549435082228750797e-38f;   // == max(tiny, u0) in fp32
    return -logf(-logf(u));
}

__device__ __forceinline__ unsigned orderf(float f) {
    unsigned u = __float_as_uint(f);
    return (u & 0x80000000u) ? ~u : (u | 0x80000000u);
}

__device__ __forceinline__ unsigned long long gpack(float val, int v) {
    return ((unsigned long long)orderf(val) << 32) |
           (0xFFFFFFFFu - (unsigned)v);
}

__device__ __forceinline__ int decode_sid(unsigned long long slot) {
    return (int)(0xFFFFFFFFu - (unsigned)(slot & 0xFFFFFFFFull));
}

// ---------------- fragment-order split precompute (any W, any K) -------------
// dst[(g*nks + ks)*32 + l]: n = 8g + (l>>2), k = 16ks + 2(l&3)
__global__ __launch_bounds__(256) void wfrag_kernel(const float* __restrict__ W,
                                                    uint4* __restrict__ dst,
                                                    int K) {
    size_t i = (size_t)blockIdx.x * 256 + threadIdx.x;
    int nks = K >> 4;
    int l  = (int)(i & 31);
    int gs = (int)(i >> 5);
    int ks = gs % nks;
    int g  = gs / nks;
    int n = 8 * g + (l >> 2);
    int k = 16 * ks + 2 * (l & 3);
    const float* row = W + (size_t)n * K + k;
    float2 x0 = *(const float2*)(row);
    float2 x1 = *(const float2*)(row + 8);
    unsigned short a1, a2, b1, b2, c1, c2, d1, d2;
    split2(x0.x, a1, a2); split2(x0.y, b1, b2);
    split2(x1.x, c1, c2); split2(x1.y, d1, d2);
    uint4 p;
    p.x = pack_lohi(a1, b1);   // w1 b0
    p.y = pack_lohi(c1, d1);   // w1 b1
    p.z = pack_lohi(a2, b2);   // w2 b0
    p.w = pack_lohi(c2, d2);   // w2 b1
    dst[i] = p;
}

// ---------------- init: h0 = concat(init_hidden, att_embedding) --------------
__global__ void init_kernel(const float* __restrict__ init_hidden,
                            const float* __restrict__ att) {
    int i = blockIdx.x * blockDim.x + threadIdx.x;   // [0, B*H)
    int b = i / HH, u = i % HH;
    g_h[i] = (u < DINIT) ? init_hidden[b * DINIT + u]
                         : att[b * DATT + (u - DINIT)];
}

// ---------------- gates via HMMA (fragment-split, fused id record) -----------
// blocks [0,24):  gi = x(gathered emb) @ W_ih^T + b_ih   (K=512)
// blocks [24,48): gh = h @ W_hh^T + b_hh                 (K=1024)
__global__ __launch_bounds__(256, 2) void gates_hmma(
    const float* __restrict__ emb, const int* __restrict__ inputs,
    const float* __restrict__ bih, const float* __restrict__ bhh,
    float* __restrict__ ids_out, int t, int write_ids) {

    __shared__ __align__(16) unsigned short sH1[64 * WP];
    __shared__ __align__(16) unsigned short sH2[64 * WP];
    __shared__ const float* rowp[64];

    const int tid = threadIdx.x;
    const int wid = tid >> 5, lid = tid & 31;

    const bool gi_part = blockIdx.x < 24;
    const int nb   = gi_part ? blockIdx.x : blockIdx.x - 24;
    const int K    = gi_part ? EE : HH;
    const int nkc  = K / KCH;           // 16 or 32
    const int nks  = K >> 4;            // 32 or 64
    const uint4* wf = gi_part ? g_wfih : g_wfhh;
    const float* bias = gi_part ? bih : bhh;
    float* C = gi_part ? g_gi : g_gh;

    if (tid < 64) {
        int sid = (t == 0) ? inputs[tid] : decode_sid(g_slots[tid]);
        rowp[tid] = gi_part ? (emb + (size_t)sid * EE)
                            : (g_h + (size_t)tid * HH);
        if (gi_part && blockIdx.x == 0 && write_ids && t > 0)
            ids_out[(size_t)tid * TT + (t - 1)] = (float)sid;
    }
    __syncthreads();

    const int hrow = tid >> 2, hk = (tid & 3) << 3;
    const float* hptr = rowp[hrow] + hk;

    float4 hre[2];
#pragma unroll
    for (int j = 0; j < 2; ++j) hre[j] = *(const float4*)(hptr + 4 * j);

    const int m0 = (wid & 1) << 5;
    const int n0 = (wid >> 1) << 5;

    const int gw = nb * 16 + (n0 >> 3);
    const uint4* wfp = wf + ((size_t)gw * nks) * 32 + lid;

    float acc[2][4][4];
#pragma unroll
    for (int mm = 0; mm < 2; ++mm)
#pragma unroll
        for (int nn = 0; nn < 4; ++nn)
#pragma unroll
            for (int q = 0; q < 4; ++q) acc[mm][nn][q] = 0.0f;

    const uint32_t aH1 = smem_u32(sH1), aH2 = smem_u32(sH2);
    const int lj = lid >> 3, lr = lid & 7;

    uint4 bcur[4], bnxt[4];
#pragma unroll
    for (int nn = 0; nn < 4; ++nn) bcur[nn] = wfp[(size_t)nn * nks * 32];

    for (int c = 0; c < nkc; ++c) {
        {
            unsigned short s1[8], s2[8];
            const float* xs = (const float*)hre;
#pragma unroll
            for (int j = 0; j < 8; ++j) split2(xs[j], s1[j], s2[j]);
            uint32_t* d1 = (uint32_t*)&sH1[hrow * WP + hk];
            uint32_t* d2 = (uint32_t*)&sH2[hrow * WP + hk];
#pragma unroll
            for (int j = 0; j < 4; ++j) {
                d1[j] = pack_lohi(s1[2 * j], s1[2 * j + 1]);
                d2[j] = pack_lohi(s2[2 * j], s2[2 * j + 1]);
            }
        }
        __syncthreads();

        if (c + 1 < nkc) {
            const float* hn = hptr + (c + 1) * KCH;
#pragma unroll
            for (int j = 0; j < 2; ++j) hre[j] = *(const float4*)(hn + 4 * j);
        }

#pragma unroll
        for (int ks = 0; ks < 2; ++ks) {
            const int kb = ks << 4;
            const int ksi = c * 2 + ks;

            if (ksi + 1 < nks) {
#pragma unroll
                for (int nn = 0; nn < 4; ++nn)
                    bnxt[nn] = wfp[((size_t)nn * nks + (ksi + 1)) * 32];
            }

            uint32_t a1[2][4], a2[2][4];
#pragma unroll
            for (int mm = 0; mm < 2; ++mm) {
                int row = m0 + (mm << 4) + ((lj & 1) << 3) + lr;
                int col = kb + ((lj >> 1) << 3);
                uint32_t off = (uint32_t)(row * WP + col) * 2;
                ldsm4(a1[mm], aH1 + off);
                ldsm4(a2[mm], aH2 + off);
            }

#pragma unroll
            for (int mm = 0; mm < 2; ++mm)
#pragma unroll
                for (int nn = 0; nn < 4; ++nn) {
                    mma16816(acc[mm][nn], a1[mm], bcur[nn].x, bcur[nn].y);
                    mma16816(acc[mm][nn], a2[mm], bcur[nn].x, bcur[nn].y);
                    mma16816(acc[mm][nn], a1[mm], bcur[nn].z, bcur[nn].w);
                }
#pragma unroll
            for (int nn = 0; nn < 4; ++nn) bcur[nn] = bnxt[nn];
        }
        __syncthreads();
    }

    // epilogue: write gates rows (batch) x cols (gate units), add bias
#pragma unroll
    for (int nn = 0; nn < 4; ++nn) {
        int n = nb * 128 + n0 + (nn << 3) + ((lid & 3) << 1);
        float2 bias2 = *(const float2*)(bias + n);
#pragma unroll
        for (int mm = 0; mm < 2; ++mm) {
            int b0i = m0 + (mm << 4) + (lid >> 2);
            *(float2*)(C + (size_t)b0i * G3 + n) =
                make_float2(acc[mm][nn][0] + bias2.x, acc[mm][nn][1] + bias2.y);
            *(float2*)(C + (size_t)(b0i + 8) * G3 + n) =
                make_float2(acc[mm][nn][2] + bias2.x, acc[mm][nn][3] + bias2.y);
        }
    }
}

// ---------------- logits via HMMA + fused gumbel-max sampling ----------------
__global__ __launch_bounds__(256, 2) void logits_hmma(
    const float* __restrict__ bout, float* __restrict__ out,
    unsigned k0, unsigned k1) {

    __shared__ __align__(16) unsigned short sH1[64 * WP];
    __shared__ __align__(16) unsigned short sH2[64 * WP];

    const int tid = threadIdx.x;
    const int wid = tid >> 5, lid = tid & 31;
    const int v0 = blockIdx.x * 128;

    const int hrow = tid >> 2, hk = (tid & 3) << 3;
    const float* hptr = g_h + (size_t)hrow * HH + hk;

    float4 hre[2];
#pragma unroll
    for (int j = 0; j < 2; ++j) hre[j] = *(const float4*)(hptr + 4 * j);

    const int m0 = (wid & 1) << 5;
    const int n0 = (wid >> 1) << 5;

    const int gw = blockIdx.x * 16 + (n0 >> 3);
    const uint4* wfp = g_wf + ((size_t)gw * NKS) * 32 + lid;

    float acc[2][4][4];
#pragma unroll
    for (int mm = 0; mm < 2; ++mm)
#pragma unroll
        for (int nn = 0; nn < 4; ++nn)
#pragma unroll
            for (int q = 0; q < 4; ++q) acc[mm][nn][q] = 0.0f;

    const uint32_t aH1 = smem_u32(sH1), aH2 = smem_u32(sH2);
    const int lj = lid >> 3, lr = lid & 7;

    uint4 bcur[4], bnxt[4];
#pragma unroll
    for (int nn = 0; nn < 4; ++nn) bcur[nn] = wfp[(size_t)nn * NKS * 32];

    for (int c = 0; c < NKC; ++c) {
        {
            unsigned short s1[8], s2[8];
            const float* xs = (const float*)hre;
#pragma unroll
            for (int j = 0; j < 8; ++j) split2(xs[j], s1[j], s2[j]);
            uint32_t* d1 = (uint32_t*)&sH1[hrow * WP + hk];
            uint32_t* d2 = (uint32_t*)&sH2[hrow * WP + hk];
#pragma unroll
            for (int j = 0; j < 4; ++j) {
                d1[j] = pack_lohi(s1[2 * j], s1[2 * j + 1]);
                d2[j] = pack_lohi(s2[2 * j], s2[2 * j + 1]);
            }
        }
        __syncthreads();

        if (c + 1 < NKC) {
            const float* hn = hptr + (c + 1) * KCH;
#pragma unroll
            for (int j = 0; j < 2; ++j) hre[j] = *(const float4*)(hn + 4 * j);
        }

#pragma unroll
        for (int ks = 0; ks < 2; ++ks) {
            const int kb = ks << 4;
            const int ksi = c * 2 + ks;

            if (ksi + 1 < NKS) {
#pragma unroll
                for (int nn = 0; nn < 4; ++nn)
                    bnxt[nn] = wfp[((size_t)nn * NKS + (ksi + 1)) * 32];
            }

            uint32_t a1[2][4], a2[2][4];
#pragma unroll
            for (int mm = 0; mm < 2; ++mm) {
                int row = m0 + (mm << 4) + ((lj & 1) << 3) + lr;
                int col = kb + ((lj >> 1) << 3);
                uint32_t off = (uint32_t)(row * WP + col) * 2;
                ldsm4(a1[mm], aH1 + off);
                ldsm4(a2[mm], aH2 + off);
            }

#pragma unroll
            for (int mm = 0; mm < 2; ++mm)
#pragma unroll
                for (int nn = 0; nn < 4; ++nn) {
                    mma16816(acc[mm][nn], a1[mm], bcur[nn].x, bcur[nn].y);
                    mma16816(acc[mm][nn], a2[mm], bcur[nn].x, bcur[nn].y);
                    mma16816(acc[mm][nn], a1[mm], bcur[nn].z, bcur[nn].w);
                }
#pragma unroll
            for (int nn = 0; nn < 4; ++nn) bcur[nn] = bnxt[nn];
        }
        __syncthreads();
    }

    // ---- epilogue: add bias, write logits, fused gumbel partial argmax ----
    unsigned long long bst[2][2] = {{0ull, 0ull}, {0ull, 0ull}};
#pragma unroll
    for (int nn = 0; nn < 4; ++nn) {
        int v = v0 + n0 + (nn << 3) + ((lid & 3) << 1);
        float2 bias = *(const float2*)(bout + v);
#pragma unroll
        for (int mm = 0; mm < 2; ++mm) {
            int b0i = m0 + (mm << 4) + (lid >> 2);
            float v00 = acc[mm][nn][0] + bias.x;
            float v01 = acc[mm][nn][1] + bias.y;
            float v10 = acc[mm][nn][2] + bias.x;
            float v11 = acc[mm][nn][3] + bias.y;
            *(float2*)(out + (size_t)b0i * VV + v)       = make_float2(v00, v01);
            *(float2*)(out + (size_t)(b0i + 8) * VV + v) = make_float2(v10, v11);

            unsigned e0 = (unsigned)(b0i * VV + v);
            unsigned e1 = (unsigned)((b0i + 8) * VV + v);
            unsigned long long p;
            p = gpack(v00 + gumbel_from_bits(jax_bits32(k0, k1, e0)), v);
            if (p > bst[mm][0]) bst[mm][0] = p;
            p = gpack(v01 + gumbel_from_bits(jax_bits32(k0, k1, e0 + 1)), v + 1);
            if (p > bst[mm][0]) bst[mm][0] = p;
            p = gpack(v10 + gumbel_from_bits(jax_bits32(k0, k1, e1)), v);
            if (p > bst[mm][1]) bst[mm][1] = p;
            p = gpack(v11 + gumbel_from_bits(jax_bits32(k0, k1, e1 + 1)), v + 1);
            if (p > bst[mm][1]) bst[mm][1] = p;
        }
    }
#pragma unroll
    for (int mm = 0; mm < 2; ++mm)
#pragma unroll
        for (int r = 0; r < 2; ++r) {
            unsigned long long x = bst[mm][r];
            unsigned long long y = __shfl_xor_sync(0xFFFFFFFFu, x, 1);
            if (y > x) x = y;
            y = __shfl_xor_sync(0xFFFFFFFFu, x, 2);
            if (y > x) x = y;
            if ((lid & 3) == 0) {
                int row = m0 + (mm << 4) + (lid >> 2) + 8 * r;
                atomicMax(&g_slots[row], x);
            }
        }
}

// ---------------- GRU elementwise update + slot reset ------------------------
__global__ void hnew_kernel() {
    int i = blockIdx.x * blockDim.x + threadIdx.x;   // [0, B*H)
    int b = i / HH, u = i % HH;
    const float* gi = g_gi + (size_t)b * G3;
    const float* gh = g_gh + (size_t)b * G3;
    float ir = gi[u], iz = gi[HH + u], in_ = gi[2 * HH + u];
    float hr = gh[u], hz = gh[HH + u], hn  = gh[2 * HH + u];
    float r = 1.0f / (1.0f + expf(-(ir + hr)));
    float z = 1.0f / (1.0f + expf(-(iz + hz)));
    float n = tanhf(in_ + r * hn);
    float h = g_h[i];
    g_h[i] = (1.0f - z) * n + z * h;
    if (i < BB) g_slots[i] = 0ull;   // reset argmax slots before logits+sample
}

// ---------------- final ids record (last step) -------------------------------
__global__ void record_final(float* __restrict__ ids_out, int write_ids) {
    int b = threadIdx.x;
    if (b < BB && write_ids)
        ids_out[(size_t)b * TT + (TT - 1)] =
            (float)decode_sid(g_slots[b]);
}

// ---------------- launch -----------------------------------------------------
extern "C" void kernel_launch(void* const* d_in, const int* in_sizes, int n_in,
                              void* d_out, int out_size) {
    (void)in_sizes;
    int o = (n_in >= 11) ? 1 : 0;   // optional max_length scalar at slot 1
    const int*   inputs      = (const int*)  d_in[0];
    const float* init_hidden = (const float*)d_in[1 + o];
    const float* att         = (const float*)d_in[2 + o];
    const float* emb         = (const float*)d_in[3 + o];
    const float* W_ih        = (const float*)d_in[4 + o];
    const float* W_hh        = (const float*)d_in[5 + o];
    const float* b_ih        = (const float*)d_in[6 + o];
    const float* b_hh        = (const float*)d_in[7 + o];
    const float* W_out       = (const float*)d_in[8 + o];
    const float* b_out       = (const float*)d_in[9 + o];
    float* out = (float*)d_out;

    const long long TBV = (long long)TT * BB * VV;
    const int has_ids   = ((long long)out_size >= TBV + (long long)BB * TT) ? 1 : 0;
    float* ids_out = out + TBV;

    // per-step PRNG keys: partitionable (fold-like) split of key(42)
    unsigned keys[TT][2];
    for (int t = 0; t < TT; ++t) {
        unsigned a, b;
        tf2x32(0u, 42u, 0u, (unsigned)t, &a, &b);
        keys[t][0] = a; keys[t][1] = b;
    }

    // one-time fragment splits
    {
        uint4* wf_ptr;
        cudaGetSymbolAddress((void**)&wf_ptr, g_wf);
        wfrag_kernel<<<(NG * NKS * 32) / 256, 256>>>(W_out, wf_ptr, HH);
        cudaGetSymbolAddress((void**)&wf_ptr, g_wfih);
        wfrag_kernel<<<(NGG * (EE / 16) * 32) / 256, 256>>>(W_ih, wf_ptr, EE);
        cudaGetSymbolAddress((void**)&wf_ptr, g_wfhh);
        wfrag_kernel<<<(NGG * (HH / 16) * 32) / 256, 256>>>(W_hh, wf_ptr, HH);
    }
    init_kernel<<<(BB * HH) / 256, 256>>>(init_hidden, att);
    for (int t = 0; t < TT; ++t) {
        gates_hmma<<<48, 256>>>(emb, inputs, b_ih, b_hh, ids_out, t, has_ids);
        hnew_kernel<<<(BB * HH) / 256, 256>>>();
        logits_hmma<<<VV / 128, 256>>>(b_out, out + (size_t)t * BB * VV,
                                       keys[t][0], keys[t][1]);
    }
    record_final<<<1, 64>>>(ids_out, has_ids);
}